// round 4
// baseline (speedup 1.0000x reference)
#include <cuda_runtime.h>
#include <cuda_bf16.h>
#include <math.h>

// Problem constants
#define BB   8
#define CC   256
#define NN   64
#define PP   256
#define SS   (BB * NN * PP)     // 131072 tokens
#define HH   4
#define DD   64
#define HID  512
#define QKV  768
#define ATTN_SCALE 0.125f
#define LN_EPS 1e-5f

// Scratch (static __device__ arrays: allocation-free per harness rules)
__device__ float g_xseq[(size_t)SS * CC];   // transposed input (shortcut 1)
__device__ float g_h   [(size_t)SS * CC];   // LN outputs (reused)
__device__ float g_qkv [(size_t)SS * QKV];  // qkv projections
__device__ float g_x2  [(size_t)SS * CC];   // residual after attention (shortcut 2)
__device__ float g_mlp [(size_t)SS * HID];  // mlp hidden
__device__ float g_y   [(size_t)SS * CC];   // attn out (tmp), then final tokenwise out

// ---------------------------------------------------------------------------
// Transpose in: x[B,C,N,P] -> g_xseq[s=(b*N+n)*P+p][c]
// ---------------------------------------------------------------------------
__global__ void k_transpose_in(const float* __restrict__ x, float* __restrict__ xseq) {
    __shared__ float tile[32][33];
    int bn = blockIdx.z;            // b*N + n
    int b = bn >> 6, n = bn & 63;
    int c0 = blockIdx.y * 32, p0 = blockIdx.x * 32;
    int tx = threadIdx.x;
    #pragma unroll
    for (int k = threadIdx.y; k < 32; k += 8) {
        int c = c0 + k;
        tile[k][tx] = x[(((size_t)b * CC + c) * NN + n) * PP + p0 + tx];
    }
    __syncthreads();
    #pragma unroll
    for (int k = threadIdx.y; k < 32; k += 8) {
        int p = p0 + k;
        xseq[((size_t)bn * PP + p) * CC + c0 + tx] = tile[tx][k];
    }
}

// ---------------------------------------------------------------------------
// Transpose out: g_y[s][c] -> out[B,C,N,P]
// ---------------------------------------------------------------------------
__global__ void k_transpose_out(const float* __restrict__ y, float* __restrict__ out) {
    __shared__ float tile[32][33];
    int bn = blockIdx.z;
    int b = bn >> 6, n = bn & 63;
    int c0 = blockIdx.y * 32, p0 = blockIdx.x * 32;
    int tx = threadIdx.x;
    #pragma unroll
    for (int k = threadIdx.y; k < 32; k += 8) {
        int p = p0 + k;
        tile[k][tx] = y[((size_t)bn * PP + p) * CC + c0 + tx];
    }
    __syncthreads();
    #pragma unroll
    for (int k = threadIdx.y; k < 32; k += 8) {
        int c = c0 + k;
        out[(((size_t)b * CC + c) * NN + n) * PP + p0 + tx] = tile[tx][k];
    }
}

// ---------------------------------------------------------------------------
// LayerNorm over C=256, one warp per token row
// ---------------------------------------------------------------------------
__global__ void k_layernorm(const float* __restrict__ in, const float* __restrict__ gamma,
                            const float* __restrict__ beta, float* __restrict__ out) {
    int row = blockIdx.x * 8 + threadIdx.y;
    int lane = threadIdx.x;
    const float* r = in + (size_t)row * CC;
    float vals[8];
    float sum = 0.f, sq = 0.f;
    #pragma unroll
    for (int k = 0; k < 8; k++) {
        float t = r[lane + k * 32];
        vals[k] = t; sum += t; sq += t * t;
    }
    #pragma unroll
    for (int o = 16; o; o >>= 1) {
        sum += __shfl_xor_sync(0xffffffffu, sum, o);
        sq  += __shfl_xor_sync(0xffffffffu, sq,  o);
    }
    float mu  = sum * (1.0f / CC);
    float var = sq * (1.0f / CC) - mu * mu;
    float inv = rsqrtf(var + LN_EPS);
    float* w = out + (size_t)row * CC;
    #pragma unroll
    for (int k = 0; k < 8; k++) {
        int c = lane + k * 32;
        w[c] = (vals[k] - mu) * inv * gamma[c] + beta[c];
    }
}

// ---------------------------------------------------------------------------
// Tiled fp32 GEMM: out[m,n] = sum_k A[m,k] * W[n,k]  (+epilogue)
// A:[S,K] row-major, W:[O,K] row-major. BM=BN=64, BK=16, 256 thr, 4x4/thread.
// EPI: 0=none, 2=bias+gelu, 3=bias+residual
// ---------------------------------------------------------------------------
__device__ __forceinline__ float gelu_exact(float v) {
    return 0.5f * v * (1.0f + erff(v * 0.70710678118654752f));
}

template<int EPI>
__global__ __launch_bounds__(256) void k_gemm(
    const float* __restrict__ A, const float* __restrict__ W,
    const float* __restrict__ bias, const float* __restrict__ res,
    float* __restrict__ out, int K, int O)
{
    __shared__ float As[16][64];
    __shared__ float Bs[16][64];
    int m0 = blockIdx.y * 64;
    int n0 = blockIdx.x * 64;
    int tid = threadIdx.x;
    int lr = tid >> 2, lq = tid & 3;     // load: row (64), k-quad (4)
    int tx = tid & 15, ty = tid >> 4;    // compute: n-quad (16), m-quad (16)
    float acc[4][4] = {};

    for (int k0 = 0; k0 < K; k0 += 16) {
        float4 a = *(const float4*)&A[(size_t)(m0 + lr) * K + k0 + lq * 4];
        float4 b = *(const float4*)&W[(size_t)(n0 + lr) * K + k0 + lq * 4];
        As[lq * 4 + 0][lr] = a.x; As[lq * 4 + 1][lr] = a.y;
        As[lq * 4 + 2][lr] = a.z; As[lq * 4 + 3][lr] = a.w;
        Bs[lq * 4 + 0][lr] = b.x; Bs[lq * 4 + 1][lr] = b.y;
        Bs[lq * 4 + 2][lr] = b.z; Bs[lq * 4 + 3][lr] = b.w;
        __syncthreads();
        #pragma unroll
        for (int k = 0; k < 16; k++) {
            float4 av = *(const float4*)&As[k][ty * 4];
            float4 bv = *(const float4*)&Bs[k][tx * 4];
            acc[0][0] += av.x * bv.x; acc[0][1] += av.x * bv.y; acc[0][2] += av.x * bv.z; acc[0][3] += av.x * bv.w;
            acc[1][0] += av.y * bv.x; acc[1][1] += av.y * bv.y; acc[1][2] += av.y * bv.z; acc[1][3] += av.y * bv.w;
            acc[2][0] += av.z * bv.x; acc[2][1] += av.z * bv.y; acc[2][2] += av.z * bv.z; acc[2][3] += av.z * bv.w;
            acc[3][0] += av.w * bv.x; acc[3][1] += av.w * bv.y; acc[3][2] += av.w * bv.z; acc[3][3] += av.w * bv.w;
        }
        __syncthreads();
    }

    int nbase = n0 + tx * 4;
    float4 bv4 = make_float4(0.f, 0.f, 0.f, 0.f);
    if (EPI >= 2) bv4 = *(const float4*)&bias[nbase];
    #pragma unroll
    for (int i = 0; i < 4; i++) {
        int m = m0 + ty * 4 + i;
        float4 v = make_float4(acc[i][0], acc[i][1], acc[i][2], acc[i][3]);
        if (EPI >= 2) { v.x += bv4.x; v.y += bv4.y; v.z += bv4.z; v.w += bv4.w; }
        if (EPI == 2) {
            v.x = gelu_exact(v.x); v.y = gelu_exact(v.y);
            v.z = gelu_exact(v.z); v.w = gelu_exact(v.w);
        }
        if (EPI == 3) {
            float4 r = *(const float4*)&res[(size_t)m * O + nbase];
            v.x += r.x; v.y += r.y; v.z += r.z; v.w += r.w;
        }
        *(float4*)&out[(size_t)m * O + nbase] = v;
    }
}

// ---------------------------------------------------------------------------
// Fused attention: one CTA per (seq, head). 256 threads = 256 query rows.
// Static 32KB smem. K/V processed in 4 chunks of 64 keys each.
// q and o accumulator in registers; online softmax.
// ---------------------------------------------------------------------------
__global__ __launch_bounds__(256) void k_attn(const float* __restrict__ qkv,
                                              float* __restrict__ o_out)
{
    __shared__ float Ks[64][64];
    __shared__ float Vs[64][64];
    int sq = blockIdx.x;             // sequence (0..511)
    int h  = blockIdx.y;             // head (0..3)
    int tid = threadIdx.x;           // query row p

    // per-thread q row (channels h*64..h*64+63 of token sq*256+tid)
    const float* qrow = qkv + ((size_t)sq * PP + tid) * QKV + h * DD;
    float q[64];
    #pragma unroll
    for (int d = 0; d < 64; d += 4) {
        float4 t = *(const float4*)&qrow[d];
        q[d] = t.x; q[d + 1] = t.y; q[d + 2] = t.z; q[d + 3] = t.w;
    }

    float m = -1e30f, l = 0.f;
    float o[64];
    #pragma unroll
    for (int d = 0; d < 64; d++) o[d] = 0.f;

    for (int c0 = 0; c0 < PP; c0 += 64) {
        __syncthreads();
        // cooperative load of 64 K rows and 64 V rows (coalesced 16 float4/row)
        for (int i = tid; i < 64 * 16; i += 256) {
            int j = i >> 4, quad = i & 15;
            const float* rowp = qkv + ((size_t)sq * PP + c0 + j) * QKV + h * DD;
            *(float4*)&Ks[j][quad * 4] = *(const float4*)&rowp[256 + quad * 4];  // k channels
            *(float4*)&Vs[j][quad * 4] = *(const float4*)&rowp[512 + quad * 4];  // v channels
        }
        __syncthreads();

        for (int j = 0; j < 64; j++) {
            const float* kr = Ks[j];
            float s = 0.f;
            #pragma unroll
            for (int d = 0; d < 64; d += 4) {
                float4 kv = *(const float4*)&kr[d];
                s += q[d] * kv.x + q[d + 1] * kv.y + q[d + 2] * kv.z + q[d + 3] * kv.w;
            }
            s *= ATTN_SCALE;
            float mn = fmaxf(m, s);
            float alpha = __expf(m - mn);
            float p = __expf(s - mn);
            l = l * alpha + p;
            const float* vr = Vs[j];
            #pragma unroll
            for (int d = 0; d < 64; d += 4) {
                float4 vv = *(const float4*)&vr[d];
                o[d]     = o[d]     * alpha + p * vv.x;
                o[d + 1] = o[d + 1] * alpha + p * vv.y;
                o[d + 2] = o[d + 2] * alpha + p * vv.z;
                o[d + 3] = o[d + 3] * alpha + p * vv.w;
            }
            m = mn;
        }
    }

    float inv = 1.0f / l;
    float* orow = o_out + ((size_t)sq * PP + tid) * CC + h * DD;
    #pragma unroll
    for (int d = 0; d < 64; d += 4) {
        float4 v = make_float4(o[d] * inv, o[d + 1] * inv, o[d + 2] * inv, o[d + 3] * inv);
        *(float4*)&orow[d] = v;
    }
}

// ---------------------------------------------------------------------------
extern "C" void kernel_launch(void* const* d_in, const int* in_sizes, int n_in,
                              void* d_out, int out_size)
{
    const float* x     = (const float*)d_in[0];
    const float* Wqkv  = (const float*)d_in[1];
    const float* Wproj = (const float*)d_in[2];
    const float* bproj = (const float*)d_in[3];
    const float* ln1g  = (const float*)d_in[4];
    const float* ln1b  = (const float*)d_in[5];
    const float* ln2g  = (const float*)d_in[6];
    const float* ln2b  = (const float*)d_in[7];
    const float* Wm1   = (const float*)d_in[8];
    const float* bm1   = (const float*)d_in[9];
    const float* Wm2   = (const float*)d_in[10];
    const float* bm2   = (const float*)d_in[11];
    float* out = (float*)d_out;

    float *p_xseq, *p_h, *p_qkv, *p_x2, *p_mlp, *p_y;
    cudaGetSymbolAddress((void**)&p_xseq, g_xseq);
    cudaGetSymbolAddress((void**)&p_h,    g_h);
    cudaGetSymbolAddress((void**)&p_qkv,  g_qkv);
    cudaGetSymbolAddress((void**)&p_x2,   g_x2);
    cudaGetSymbolAddress((void**)&p_mlp,  g_mlp);
    cudaGetSymbolAddress((void**)&p_y,    g_y);

    dim3 tb(32, 8);
    // 1) transpose to token-major
    k_transpose_in<<<dim3(PP / 32, CC / 32, BB * NN), tb>>>(x, p_xseq);
    // 2) LN1
    k_layernorm<<<SS / 8, tb>>>(p_xseq, ln1g, ln1b, p_h);
    // 3) qkv = h @ Wqkv^T (no bias)
    k_gemm<0><<<dim3(QKV / 64, SS / 64), 256>>>(p_h, Wqkv, nullptr, nullptr, p_qkv, CC, QKV);
    // 4) fused attention -> g_y (tokenwise o)
    k_attn<<<dim3(BB * NN, HH), 256>>>(p_qkv, p_y);
    // 5) proj + bias + residual(x_seq) -> g_x2
    k_gemm<3><<<dim3(CC / 64, SS / 64), 256>>>(p_y, Wproj, bproj, p_xseq, p_x2, CC, CC);
    // 6) LN2
    k_layernorm<<<SS / 8, tb>>>(p_x2, ln2g, ln2b, p_h);
    // 7) mlp1 + bias + gelu -> g_mlp
    k_gemm<2><<<dim3(HID / 64, SS / 64), 256>>>(p_h, Wm1, bm1, nullptr, p_mlp, CC, HID);
    // 8) mlp2 + bias + residual(x2) -> g_y
    k_gemm<3><<<dim3(CC / 64, SS / 64), 256>>>(p_mlp, Wm2, bm2, p_x2, p_y, HID, CC);
    // 9) transpose back to [B,C,N,P]
    k_transpose_out<<<dim3(PP / 32, CC / 32, BB * NN), tb>>>(p_y, out);
}

// round 6
// speedup vs baseline: 2.3725x; 2.3725x over previous
#include <cuda_runtime.h>
#include <cuda_bf16.h>
#include <math.h>
#include <stdint.h>

// Problem constants
#define BB   8
#define CC   256
#define NN   64
#define PP   256
#define SS   (BB * NN * PP)     // 131072 tokens
#define HH   4
#define DD   64
#define HID  512
#define QKV  768
#define ATTN_SCALE 0.125f
#define LN_EPS 1e-5f

typedef __nv_bfloat16 bf16;
typedef unsigned int u32;

// Scratch (static __device__ arrays: allocation-free per harness rules)
__device__ float g_xseq[(size_t)SS * CC];   // transposed input (shortcut 1), fp32
__device__ float g_qkv [(size_t)SS * QKV];  // qkv projections, fp32
__device__ float g_x2  [(size_t)SS * CC];   // residual after attention, fp32
__device__ float g_y   [(size_t)SS * CC];   // final tokenwise out, fp32
__device__ bf16  g_hb  [(size_t)SS * CC];   // LN outputs (bf16 GEMM input)
__device__ bf16  g_ab  [(size_t)SS * CC];   // attn out (bf16 GEMM input)
__device__ bf16  g_mb  [(size_t)SS * HID];  // mlp hidden (bf16 GEMM input)
__device__ bf16  g_wq  [QKV * CC];          // bf16 weights
__device__ bf16  g_wp  [CC * CC];
__device__ bf16  g_w1  [HID * CC];
__device__ bf16  g_w2  [CC * HID];

// ---------------------------------------------------------------------------
__global__ void k_f2b(const float* __restrict__ s, bf16* __restrict__ d, int n) {
    int i = blockIdx.x * 256 + threadIdx.x;
    if (i < n) d[i] = __float2bfloat16(s[i]);
}

// ---------------------------------------------------------------------------
// Transpose in: x[B,C,N,P] -> g_xseq[s=(b*N+n)*P+p][c]
// ---------------------------------------------------------------------------
__global__ void k_transpose_in(const float* __restrict__ x, float* __restrict__ xseq) {
    __shared__ float tile[32][33];
    int bn = blockIdx.z;
    int b = bn >> 6, n = bn & 63;
    int c0 = blockIdx.y * 32, p0 = blockIdx.x * 32;
    int tx = threadIdx.x;
    #pragma unroll
    for (int k = threadIdx.y; k < 32; k += 8) {
        tile[k][tx] = x[(((size_t)b * CC + c0 + k) * NN + n) * PP + p0 + tx];
    }
    __syncthreads();
    #pragma unroll
    for (int k = threadIdx.y; k < 32; k += 8) {
        xseq[((size_t)bn * PP + p0 + k) * CC + c0 + tx] = tile[tx][k];
    }
}

__global__ void k_transpose_out(const float* __restrict__ y, float* __restrict__ out) {
    __shared__ float tile[32][33];
    int bn = blockIdx.z;
    int b = bn >> 6, n = bn & 63;
    int c0 = blockIdx.y * 32, p0 = blockIdx.x * 32;
    int tx = threadIdx.x;
    #pragma unroll
    for (int k = threadIdx.y; k < 32; k += 8) {
        tile[k][tx] = y[((size_t)bn * PP + p0 + k) * CC + c0 + tx];
    }
    __syncthreads();
    #pragma unroll
    for (int k = threadIdx.y; k < 32; k += 8) {
        out[(((size_t)b * CC + c0 + k) * NN + n) * PP + p0 + tx] = tile[tx][k];
    }
}

// ---------------------------------------------------------------------------
// LayerNorm over C=256 -> bf16 output
// ---------------------------------------------------------------------------
__global__ void k_layernorm(const float* __restrict__ in, const float* __restrict__ gamma,
                            const float* __restrict__ beta, bf16* __restrict__ out) {
    int row = blockIdx.x * 8 + threadIdx.y;
    int lane = threadIdx.x;
    const float* r = in + (size_t)row * CC;
    float vals[8];
    float sum = 0.f, sq = 0.f;
    #pragma unroll
    for (int k = 0; k < 8; k++) {
        float t = r[lane + k * 32];
        vals[k] = t; sum += t; sq += t * t;
    }
    #pragma unroll
    for (int o = 16; o; o >>= 1) {
        sum += __shfl_xor_sync(0xffffffffu, sum, o);
        sq  += __shfl_xor_sync(0xffffffffu, sq,  o);
    }
    float mu  = sum * (1.0f / CC);
    float var = sq * (1.0f / CC) - mu * mu;
    float inv = rsqrtf(var + LN_EPS);
    bf16* w = out + (size_t)row * CC;
    #pragma unroll
    for (int k = 0; k < 8; k++) {
        int c = lane + k * 32;
        w[c] = __float2bfloat16((vals[k] - mu) * inv * gamma[c] + beta[c]);
    }
}

// ---------------------------------------------------------------------------
// Tensor-core bf16 GEMM: out[m,n] = sum_k A[m,k]*W[n,k]  (+epilogue)
// BM=BN=128, BK=32, 256 threads = 8 warps (2x4), each warp 64x32 via m16n8k16.
// EPI: 0=none, 2=bias+gelu, 3=bias+residual. OUTBF: 0=float out, 1=bf16 out.
// ---------------------------------------------------------------------------
__device__ __forceinline__ float gelu_exact(float v) {
    return 0.5f * v * (1.0f + erff(v * 0.70710678118654752f));
}

#define ST 40   // smem row stride in bf16 elems (padded; 80B, 16B-aligned)

__device__ __forceinline__ void ldsm_x4(u32* r, const bf16* p) {
    u32 addr = (u32)__cvta_generic_to_shared((const void*)p);
    asm volatile("ldmatrix.sync.aligned.m8n8.x4.shared.b16 {%0,%1,%2,%3}, [%4];"
                 : "=r"(r[0]), "=r"(r[1]), "=r"(r[2]), "=r"(r[3]) : "r"(addr));
}
__device__ __forceinline__ void ldsm_x2(u32* r, const bf16* p) {
    u32 addr = (u32)__cvta_generic_to_shared((const void*)p);
    asm volatile("ldmatrix.sync.aligned.m8n8.x2.shared.b16 {%0,%1}, [%2];"
                 : "=r"(r[0]), "=r"(r[1]) : "r"(addr));
}
__device__ __forceinline__ void mma_bf16(float* c, const u32* a, const u32* b) {
    asm volatile("mma.sync.aligned.m16n8k16.row.col.f32.bf16.bf16.f32 "
                 "{%0,%1,%2,%3}, {%4,%5,%6,%7}, {%8,%9}, {%0,%1,%2,%3};"
                 : "+f"(c[0]), "+f"(c[1]), "+f"(c[2]), "+f"(c[3])
                 : "r"(a[0]), "r"(a[1]), "r"(a[2]), "r"(a[3]), "r"(b[0]), "r"(b[1]));
}

template<int EPI, int OUTBF>
__global__ __launch_bounds__(256) void k_gemm_tc(
    const bf16* __restrict__ A, const bf16* __restrict__ W,
    const float* __restrict__ bias, const float* __restrict__ res,
    float* __restrict__ outf, bf16* __restrict__ outb, int K, int O)
{
    __shared__ bf16 As[128 * ST];
    __shared__ bf16 Bs[128 * ST];
    int tid = threadIdx.x;
    int wid = tid >> 5, lane = tid & 31;
    int warp_m = wid >> 2, warp_n = wid & 3;
    int m0 = blockIdx.y * 128, n0 = blockIdx.x * 128;

    float acc[4][4][4];
    #pragma unroll
    for (int i = 0; i < 4; i++)
        #pragma unroll
        for (int j = 0; j < 4; j++)
            #pragma unroll
            for (int t = 0; t < 4; t++) acc[i][j][t] = 0.f;

    int lrw = tid >> 2, lcc = (tid & 3) * 8;   // load row, col-chunk
    uint4 ra0, ra1, rb0, rb1;

    // prologue: tile 0
    ra0 = *(const uint4*)&A[(size_t)(m0 + lrw) * K + lcc];
    ra1 = *(const uint4*)&A[(size_t)(m0 + 64 + lrw) * K + lcc];
    rb0 = *(const uint4*)&W[(size_t)(n0 + lrw) * K + lcc];
    rb1 = *(const uint4*)&W[(size_t)(n0 + 64 + lrw) * K + lcc];
    *(uint4*)&As[lrw * ST + lcc] = ra0;
    *(uint4*)&As[(lrw + 64) * ST + lcc] = ra1;
    *(uint4*)&Bs[lrw * ST + lcc] = rb0;
    *(uint4*)&Bs[(lrw + 64) * ST + lcc] = rb1;

    int KT = K >> 5;
    int arow = (lane & 15), akk = (lane >> 4) * 8;
    int brow = (lane & 7),  bkk = ((lane >> 3) & 1) * 8;

    for (int kt = 0; kt < KT; kt++) {
        __syncthreads();
        if (kt + 1 < KT) {
            int kb = (kt + 1) * 32;
            ra0 = *(const uint4*)&A[(size_t)(m0 + lrw) * K + kb + lcc];
            ra1 = *(const uint4*)&A[(size_t)(m0 + 64 + lrw) * K + kb + lcc];
            rb0 = *(const uint4*)&W[(size_t)(n0 + lrw) * K + kb + lcc];
            rb1 = *(const uint4*)&W[(size_t)(n0 + 64 + lrw) * K + kb + lcc];
        }
        #pragma unroll
        for (int kk = 0; kk < 32; kk += 16) {
            u32 afr[4][4], bfr[4][2];
            #pragma unroll
            for (int mi = 0; mi < 4; mi++)
                ldsm_x4(afr[mi], &As[(warp_m * 64 + mi * 16 + arow) * ST + kk + akk]);
            #pragma unroll
            for (int ni = 0; ni < 4; ni++)
                ldsm_x2(bfr[ni], &Bs[(warp_n * 32 + ni * 8 + brow) * ST + kk + bkk]);
            #pragma unroll
            for (int mi = 0; mi < 4; mi++)
                #pragma unroll
                for (int ni = 0; ni < 4; ni++)
                    mma_bf16(acc[mi][ni], afr[mi], bfr[ni]);
        }
        __syncthreads();
        if (kt + 1 < KT) {
            *(uint4*)&As[lrw * ST + lcc] = ra0;
            *(uint4*)&As[(lrw + 64) * ST + lcc] = ra1;
            *(uint4*)&Bs[lrw * ST + lcc] = rb0;
            *(uint4*)&Bs[(lrw + 64) * ST + lcc] = rb1;
        }
    }

    // epilogue
    int gp = lane >> 2, tin = lane & 3;
    #pragma unroll
    for (int ni = 0; ni < 4; ni++) {
        int col = n0 + warp_n * 32 + ni * 8 + tin * 2;
        float bx = 0.f, by = 0.f;
        if (EPI >= 2) { float2 b2 = *(const float2*)&bias[col]; bx = b2.x; by = b2.y; }
        #pragma unroll
        for (int mi = 0; mi < 4; mi++) {
            int row = m0 + warp_m * 64 + mi * 16 + gp;
            #pragma unroll
            for (int half = 0; half < 2; half++) {
                int r = row + half * 8;
                float vx = acc[mi][ni][half * 2 + 0] + bx;
                float vy = acc[mi][ni][half * 2 + 1] + by;
                if (EPI == 2) { vx = gelu_exact(vx); vy = gelu_exact(vy); }
                if (EPI == 3) {
                    float2 rr = *(const float2*)&res[(size_t)r * O + col];
                    vx += rr.x; vy += rr.y;
                }
                if (OUTBF) {
                    __nv_bfloat162 p;
                    p.x = __float2bfloat16(vx); p.y = __float2bfloat16(vy);
                    *(__nv_bfloat162*)&outb[(size_t)r * O + col] = p;
                } else {
                    *(float2*)&outf[(size_t)r * O + col] = make_float2(vx, vy);
                }
            }
        }
    }
}

// ---------------------------------------------------------------------------
// Fused attention: one CTA per (seq, head). 256 threads = 256 query rows.
// fp32 math; bf16 output (feeds proj GEMM).
// ---------------------------------------------------------------------------
__global__ __launch_bounds__(256) void k_attn(const float* __restrict__ qkv,
                                              bf16* __restrict__ o_out)
{
    __shared__ float Ks[64][64];
    __shared__ float Vs[64][64];
    int sq = blockIdx.x;
    int h  = blockIdx.y;
    int tid = threadIdx.x;

    const float* qrow = qkv + ((size_t)sq * PP + tid) * QKV + h * DD;
    float q[64];
    #pragma unroll
    for (int d = 0; d < 64; d += 4) {
        float4 t = *(const float4*)&qrow[d];
        q[d] = t.x; q[d + 1] = t.y; q[d + 2] = t.z; q[d + 3] = t.w;
    }

    float m = -1e30f, l = 0.f;
    float o[64];
    #pragma unroll
    for (int d = 0; d < 64; d++) o[d] = 0.f;

    for (int c0 = 0; c0 < PP; c0 += 64) {
        __syncthreads();
        for (int i = tid; i < 64 * 16; i += 256) {
            int j = i >> 4, quad = i & 15;
            const float* rowp = qkv + ((size_t)sq * PP + c0 + j) * QKV + h * DD;
            *(float4*)&Ks[j][quad * 4] = *(const float4*)&rowp[256 + quad * 4];
            *(float4*)&Vs[j][quad * 4] = *(const float4*)&rowp[512 + quad * 4];
        }
        __syncthreads();

        for (int j = 0; j < 64; j++) {
            const float* kr = Ks[j];
            float s = 0.f;
            #pragma unroll
            for (int d = 0; d < 64; d += 4) {
                float4 kv = *(const float4*)&kr[d];
                s += q[d] * kv.x + q[d + 1] * kv.y + q[d + 2] * kv.z + q[d + 3] * kv.w;
            }
            s *= ATTN_SCALE;
            float mn = fmaxf(m, s);
            float alpha = __expf(m - mn);
            float p = __expf(s - mn);
            l = l * alpha + p;
            const float* vr = Vs[j];
            #pragma unroll
            for (int d = 0; d < 64; d += 4) {
                float4 vv = *(const float4*)&vr[d];
                o[d]     = o[d]     * alpha + p * vv.x;
                o[d + 1] = o[d + 1] * alpha + p * vv.y;
                o[d + 2] = o[d + 2] * alpha + p * vv.z;
                o[d + 3] = o[d + 3] * alpha + p * vv.w;
            }
            m = mn;
        }
    }

    float inv = 1.0f / l;
    bf16* orow = o_out + ((size_t)sq * PP + tid) * CC + h * DD;
    #pragma unroll
    for (int d = 0; d < 64; d += 2) {
        __nv_bfloat162 p;
        p.x = __float2bfloat16(o[d] * inv);
        p.y = __float2bfloat16(o[d + 1] * inv);
        *(__nv_bfloat162*)&orow[d] = p;
    }
}

// ---------------------------------------------------------------------------
extern "C" void kernel_launch(void* const* d_in, const int* in_sizes, int n_in,
                              void* d_out, int out_size)
{
    const float* x     = (const float*)d_in[0];
    const float* Wqkv  = (const float*)d_in[1];
    const float* Wproj = (const float*)d_in[2];
    const float* bproj = (const float*)d_in[3];
    const float* ln1g  = (const float*)d_in[4];
    const float* ln1b  = (const float*)d_in[5];
    const float* ln2g  = (const float*)d_in[6];
    const float* ln2b  = (const float*)d_in[7];
    const float* Wm1   = (const float*)d_in[8];
    const float* bm1   = (const float*)d_in[9];
    const float* Wm2   = (const float*)d_in[10];
    const float* bm2   = (const float*)d_in[11];
    float* out = (float*)d_out;

    float *p_xseq, *p_qkv, *p_x2, *p_y;
    bf16 *p_hb, *p_ab, *p_mb, *p_wq, *p_wp, *p_w1, *p_w2;
    cudaGetSymbolAddress((void**)&p_xseq, g_xseq);
    cudaGetSymbolAddress((void**)&p_qkv,  g_qkv);
    cudaGetSymbolAddress((void**)&p_x2,   g_x2);
    cudaGetSymbolAddress((void**)&p_y,    g_y);
    cudaGetSymbolAddress((void**)&p_hb,   g_hb);
    cudaGetSymbolAddress((void**)&p_ab,   g_ab);
    cudaGetSymbolAddress((void**)&p_mb,   g_mb);
    cudaGetSymbolAddress((void**)&p_wq,   g_wq);
    cudaGetSymbolAddress((void**)&p_wp,   g_wp);
    cudaGetSymbolAddress((void**)&p_w1,   g_w1);
    cudaGetSymbolAddress((void**)&p_w2,   g_w2);

    dim3 tb(32, 8);
    // weight conversions (cheap)
    k_f2b<<<(QKV * CC + 255) / 256, 256>>>(Wqkv, p_wq, QKV * CC);
    k_f2b<<<(CC * CC + 255) / 256, 256>>>(Wproj, p_wp, CC * CC);
    k_f2b<<<(HID * CC + 255) / 256, 256>>>(Wm1, p_w1, HID * CC);
    k_f2b<<<(CC * HID + 255) / 256, 256>>>(Wm2, p_w2, CC * HID);
    // 1) transpose to token-major
    k_transpose_in<<<dim3(PP / 32, CC / 32, BB * NN), tb>>>(x, p_xseq);
    // 2) LN1 -> bf16
    k_layernorm<<<SS / 8, tb>>>(p_xseq, ln1g, ln1b, p_hb);
    // 3) qkv = h @ Wqkv^T (tensor cores, fp32 out)
    k_gemm_tc<0, 0> <<<dim3(QKV / 128, SS / 128), 256>>>(p_hb, p_wq, (const float*)0, (const float*)0, p_qkv, (bf16*)0, CC, QKV);
    // 4) fused attention -> bf16
    k_attn<<<dim3(BB * NN, HH), 256>>>(p_qkv, p_ab);
    // 5) proj + bias + residual(x_seq) -> fp32 x2
    k_gemm_tc<3, 0> <<<dim3(CC / 128, SS / 128), 256>>>(p_ab, p_wp, bproj, p_xseq, p_x2, (bf16*)0, CC, CC);
    // 6) LN2 -> bf16
    k_layernorm<<<SS / 8, tb>>>(p_x2, ln2g, ln2b, p_hb);
    // 7) mlp1 + bias + gelu -> bf16
    k_gemm_tc<2, 1> <<<dim3(HID / 128, SS / 128), 256>>>(p_hb, p_w1, bm1, (const float*)0, (float*)0, p_mb, CC, HID);
    // 8) mlp2 + bias + residual(x2) -> fp32 y
    k_gemm_tc<3, 0> <<<dim3(CC / 128, SS / 128), 256>>>(p_mb, p_w2, bm2, p_x2, p_y, (bf16*)0, HID, CC);
    // 9) transpose back
    k_transpose_out<<<dim3(PP / 32, CC / 32, BB * NN), tb>>>(p_y, out);
}

// round 7
// speedup vs baseline: 4.9215x; 2.0744x over previous
#include <cuda_runtime.h>
#include <cuda_bf16.h>
#include <math.h>
#include <stdint.h>

// Problem constants
#define BB   8
#define CC   256
#define NN   64
#define PP   256
#define SS   (BB * NN * PP)     // 131072 tokens
#define HH   4
#define DD   64
#define HID  512
#define QKV  768
#define ATTN_SCALE 0.125f
#define LN_EPS 1e-5f

typedef __nv_bfloat16 bf16;
typedef unsigned int u32;

// Scratch (static __device__ arrays: allocation-free per harness rules)
__device__ float g_xseq[(size_t)SS * CC];   // transposed input (shortcut 1), fp32
__device__ float g_x2  [(size_t)SS * CC];   // residual after attention, fp32
__device__ float g_y   [(size_t)SS * CC];   // final tokenwise out, fp32
__device__ bf16  g_qkvb[(size_t)SS * QKV];  // qkv projections, bf16
__device__ bf16  g_hb  [(size_t)SS * CC];   // LN outputs (bf16 GEMM input)
__device__ bf16  g_ab  [(size_t)SS * CC];   // attn out (bf16 GEMM input)
__device__ bf16  g_mb  [(size_t)SS * HID];  // mlp hidden (bf16 GEMM input)
__device__ bf16  g_wq  [QKV * CC];          // bf16 weights
__device__ bf16  g_wp  [CC * CC];
__device__ bf16  g_w1  [HID * CC];
__device__ bf16  g_w2  [CC * HID];

// ---------------------------------------------------------------------------
__global__ void k_f2b(const float* __restrict__ s, bf16* __restrict__ d, int n) {
    int i = blockIdx.x * 256 + threadIdx.x;
    if (i < n) d[i] = __float2bfloat16(s[i]);
}

// ---------------------------------------------------------------------------
// Transpose in: x[B,C,N,P] -> g_xseq[s=(b*N+n)*P+p][c]
// ---------------------------------------------------------------------------
__global__ void k_transpose_in(const float* __restrict__ x, float* __restrict__ xseq) {
    __shared__ float tile[32][33];
    int bn = blockIdx.z;
    int b = bn >> 6, n = bn & 63;
    int c0 = blockIdx.y * 32, p0 = blockIdx.x * 32;
    int tx = threadIdx.x;
    #pragma unroll
    for (int k = threadIdx.y; k < 32; k += 8) {
        tile[k][tx] = x[(((size_t)b * CC + c0 + k) * NN + n) * PP + p0 + tx];
    }
    __syncthreads();
    #pragma unroll
    for (int k = threadIdx.y; k < 32; k += 8) {
        xseq[((size_t)bn * PP + p0 + k) * CC + c0 + tx] = tile[tx][k];
    }
}

__global__ void k_transpose_out(const float* __restrict__ y, float* __restrict__ out) {
    __shared__ float tile[32][33];
    int bn = blockIdx.z;
    int b = bn >> 6, n = bn & 63;
    int c0 = blockIdx.y * 32, p0 = blockIdx.x * 32;
    int tx = threadIdx.x;
    #pragma unroll
    for (int k = threadIdx.y; k < 32; k += 8) {
        tile[k][tx] = y[((size_t)bn * PP + p0 + k) * CC + c0 + tx];
    }
    __syncthreads();
    #pragma unroll
    for (int k = threadIdx.y; k < 32; k += 8) {
        out[(((size_t)b * CC + c0 + k) * NN + n) * PP + p0 + tx] = tile[tx][k];
    }
}

// ---------------------------------------------------------------------------
// LayerNorm over C=256 -> bf16 output
// ---------------------------------------------------------------------------
__global__ void k_layernorm(const float* __restrict__ in, const float* __restrict__ gamma,
                            const float* __restrict__ beta, bf16* __restrict__ out) {
    int row = blockIdx.x * 8 + threadIdx.y;
    int lane = threadIdx.x;
    const float* r = in + (size_t)row * CC;
    float vals[8];
    float sum = 0.f, sq = 0.f;
    #pragma unroll
    for (int k = 0; k < 8; k++) {
        float t = r[lane + k * 32];
        vals[k] = t; sum += t; sq += t * t;
    }
    #pragma unroll
    for (int o = 16; o; o >>= 1) {
        sum += __shfl_xor_sync(0xffffffffu, sum, o);
        sq  += __shfl_xor_sync(0xffffffffu, sq,  o);
    }
    float mu  = sum * (1.0f / CC);
    float var = sq * (1.0f / CC) - mu * mu;
    float inv = rsqrtf(var + LN_EPS);
    bf16* w = out + (size_t)row * CC;
    #pragma unroll
    for (int k = 0; k < 8; k++) {
        int c = lane + k * 32;
        w[c] = __float2bfloat16((vals[k] - mu) * inv * gamma[c] + beta[c]);
    }
}

// ---------------------------------------------------------------------------
// MMA helpers
// ---------------------------------------------------------------------------
__device__ __forceinline__ float gelu_exact(float v) {
    return 0.5f * v * (1.0f + erff(v * 0.70710678118654752f));
}

#define ST 40   // GEMM smem row stride in bf16 elems (80B = 5*16B)

__device__ __forceinline__ void ldsm_x4(u32* r, const bf16* p) {
    u32 addr = (u32)__cvta_generic_to_shared((const void*)p);
    asm volatile("ldmatrix.sync.aligned.m8n8.x4.shared.b16 {%0,%1,%2,%3}, [%4];"
                 : "=r"(r[0]), "=r"(r[1]), "=r"(r[2]), "=r"(r[3]) : "r"(addr));
}
__device__ __forceinline__ void ldsm_x2(u32* r, const bf16* p) {
    u32 addr = (u32)__cvta_generic_to_shared((const void*)p);
    asm volatile("ldmatrix.sync.aligned.m8n8.x2.shared.b16 {%0,%1}, [%2];"
                 : "=r"(r[0]), "=r"(r[1]) : "r"(addr));
}
__device__ __forceinline__ void mma_bf16(float* c, const u32* a, const u32* b) {
    asm volatile("mma.sync.aligned.m16n8k16.row.col.f32.bf16.bf16.f32 "
                 "{%0,%1,%2,%3}, {%4,%5,%6,%7}, {%8,%9}, {%0,%1,%2,%3};"
                 : "+f"(c[0]), "+f"(c[1]), "+f"(c[2]), "+f"(c[3])
                 : "r"(a[0]), "r"(a[1]), "r"(a[2]), "r"(a[3]), "r"(b[0]), "r"(b[1]));
}
__device__ __forceinline__ u32 packbf2(float a, float b) {
    __nv_bfloat162 t = __float22bfloat162_rn(make_float2(a, b));
    return *(u32*)&t;
}

// ---------------------------------------------------------------------------
// Tensor-core bf16 GEMM: out[m,n] = sum_k A[m,k]*W[n,k]  (+epilogue)
// BM=BN=128, BK=32, 256 threads = 8 warps (2x4), each warp 64x32 via m16n8k16.
// EPI: 0=none, 2=bias+gelu, 3=bias+residual. OUTBF: 0=float out, 1=bf16 out.
// ---------------------------------------------------------------------------
template<int EPI, int OUTBF>
__global__ __launch_bounds__(256) void k_gemm_tc(
    const bf16* __restrict__ A, const bf16* __restrict__ W,
    const float* __restrict__ bias, const float* __restrict__ res,
    float* __restrict__ outf, bf16* __restrict__ outb, int K, int O)
{
    __shared__ bf16 As[128 * ST];
    __shared__ bf16 Bs[128 * ST];
    int tid = threadIdx.x;
    int wid = tid >> 5, lane = tid & 31;
    int warp_m = wid >> 2, warp_n = wid & 3;
    int m0 = blockIdx.y * 128, n0 = blockIdx.x * 128;

    float acc[4][4][4];
    #pragma unroll
    for (int i = 0; i < 4; i++)
        #pragma unroll
        for (int j = 0; j < 4; j++)
            #pragma unroll
            for (int t = 0; t < 4; t++) acc[i][j][t] = 0.f;

    int lrw = tid >> 2, lcc = (tid & 3) * 8;
    uint4 ra0, ra1, rb0, rb1;

    ra0 = *(const uint4*)&A[(size_t)(m0 + lrw) * K + lcc];
    ra1 = *(const uint4*)&A[(size_t)(m0 + 64 + lrw) * K + lcc];
    rb0 = *(const uint4*)&W[(size_t)(n0 + lrw) * K + lcc];
    rb1 = *(const uint4*)&W[(size_t)(n0 + 64 + lrw) * K + lcc];
    *(uint4*)&As[lrw * ST + lcc] = ra0;
    *(uint4*)&As[(lrw + 64) * ST + lcc] = ra1;
    *(uint4*)&Bs[lrw * ST + lcc] = rb0;
    *(uint4*)&Bs[(lrw + 64) * ST + lcc] = rb1;

    int KT = K >> 5;
    int arow = (lane & 15), akk = (lane >> 4) * 8;
    int brow = (lane & 7),  bkk = ((lane >> 3) & 1) * 8;

    for (int kt = 0; kt < KT; kt++) {
        __syncthreads();
        if (kt + 1 < KT) {
            int kb = (kt + 1) * 32;
            ra0 = *(const uint4*)&A[(size_t)(m0 + lrw) * K + kb + lcc];
            ra1 = *(const uint4*)&A[(size_t)(m0 + 64 + lrw) * K + kb + lcc];
            rb0 = *(const uint4*)&W[(size_t)(n0 + lrw) * K + kb + lcc];
            rb1 = *(const uint4*)&W[(size_t)(n0 + 64 + lrw) * K + kb + lcc];
        }
        #pragma unroll
        for (int kk = 0; kk < 32; kk += 16) {
            u32 afr[4][4], bfr[4][2];
            #pragma unroll
            for (int mi = 0; mi < 4; mi++)
                ldsm_x4(afr[mi], &As[(warp_m * 64 + mi * 16 + arow) * ST + kk + akk]);
            #pragma unroll
            for (int ni = 0; ni < 4; ni++)
                ldsm_x2(bfr[ni], &Bs[(warp_n * 32 + ni * 8 + brow) * ST + kk + bkk]);
            #pragma unroll
            for (int mi = 0; mi < 4; mi++)
                #pragma unroll
                for (int ni = 0; ni < 4; ni++)
                    mma_bf16(acc[mi][ni], afr[mi], bfr[ni]);
        }
        __syncthreads();
        if (kt + 1 < KT) {
            *(uint4*)&As[lrw * ST + lcc] = ra0;
            *(uint4*)&As[(lrw + 64) * ST + lcc] = ra1;
            *(uint4*)&Bs[lrw * ST + lcc] = rb0;
            *(uint4*)&Bs[(lrw + 64) * ST + lcc] = rb1;
        }
    }

    int gp = lane >> 2, tin = lane & 3;
    #pragma unroll
    for (int ni = 0; ni < 4; ni++) {
        int col = n0 + warp_n * 32 + ni * 8 + tin * 2;
        float bx = 0.f, by = 0.f;
        if (EPI >= 2) { float2 b2 = *(const float2*)&bias[col]; bx = b2.x; by = b2.y; }
        #pragma unroll
        for (int mi = 0; mi < 4; mi++) {
            int row = m0 + warp_m * 64 + mi * 16 + gp;
            #pragma unroll
            for (int half = 0; half < 2; half++) {
                int r = row + half * 8;
                float vx = acc[mi][ni][half * 2 + 0] + bx;
                float vy = acc[mi][ni][half * 2 + 1] + by;
                if (EPI == 2) { vx = gelu_exact(vx); vy = gelu_exact(vy); }
                if (EPI == 3) {
                    float2 rr = *(const float2*)&res[(size_t)r * O + col];
                    vx += rr.x; vy += rr.y;
                }
                if (OUTBF) {
                    __nv_bfloat162 p;
                    p.x = __float2bfloat16(vx); p.y = __float2bfloat16(vy);
                    *(__nv_bfloat162*)&outb[(size_t)r * O + col] = p;
                } else {
                    *(float2*)&outf[(size_t)r * O + col] = make_float2(vx, vy);
                }
            }
        }
    }
}

// ---------------------------------------------------------------------------
// Tensor-core flash attention: one CTA per (seq, head). 8 warps x 32 q-rows.
// Q fragments direct from global; K chunk (64 keys) in smem [key][d];
// V chunk transposed in smem [d][key]; online softmax on mma C fragments;
// S->P fragment reuse (C layout == A layout) for P@V.
// ---------------------------------------------------------------------------
__global__ __launch_bounds__(256) void k_attn_tc(const bf16* __restrict__ qkv,
                                                 bf16* __restrict__ o_out)
{
    __shared__ bf16 Ks[64][72];   // [key][d]   stride 144B = 9*16B
    __shared__ bf16 Vt[64][72];   // [d][key]

    int sq = blockIdx.x, h = blockIdx.y;
    int tid = threadIdx.x, wid = tid >> 5, lane = tid & 31;
    int gp = lane >> 2, tin = lane & 3;
    int brow = lane & 7, bkk = ((lane >> 3) & 1) * 8;
    const size_t tok0 = (size_t)sq * PP;
    const bf16* qb = qkv + tok0 * QKV + h * DD;          // q cols
    const bf16* kb = qkv + tok0 * QKV + 256 + h * DD;    // k cols
    const bf16* vb = qkv + tok0 * QKV + 512 + h * DD;    // v cols

    // Q fragments for this warp's 32 rows: qa[mi][kk][4]
    u32 qa[2][4][4];
    #pragma unroll
    for (int mi = 0; mi < 2; mi++) {
        int r0 = wid * 32 + mi * 16 + gp;
        #pragma unroll
        for (int kk = 0; kk < 4; kk++) {
            const bf16* p0 = qb + (size_t)r0 * QKV + kk * 16 + tin * 2;
            const bf16* p1 = qb + (size_t)(r0 + 8) * QKV + kk * 16 + tin * 2;
            qa[mi][kk][0] = *(const u32*)p0;
            qa[mi][kk][1] = *(const u32*)p1;
            qa[mi][kk][2] = *(const u32*)(p0 + 8);
            qa[mi][kk][3] = *(const u32*)(p1 + 8);
        }
    }

    float o[2][8][4];
    #pragma unroll
    for (int mi = 0; mi < 2; mi++)
        #pragma unroll
        for (int nd = 0; nd < 8; nd++)
            #pragma unroll
            for (int t = 0; t < 4; t++) o[mi][nd][t] = 0.f;
    float mrow[2][2] = {{-1e30f, -1e30f}, {-1e30f, -1e30f}};
    float lrow[2][2] = {{0.f, 0.f}, {0.f, 0.f}};

    for (int c0 = 0; c0 < PP; c0 += 64) {
        __syncthreads();
        // K chunk: 64 rows x 8 uint4
        for (int i = tid; i < 64 * 8; i += 256) {
            int j = i >> 3, q8 = i & 7;
            *(uint4*)&Ks[j][q8 * 8] = *(const uint4*)(kb + (size_t)(c0 + j) * QKV + q8 * 8);
        }
        // V chunk transposed: Vt[d][key]
        for (int i = tid; i < 64 * 32; i += 256) {
            int j = i >> 5, g = i & 31;
            const bf16* src = vb + (size_t)(c0 + j) * QKV + g * 2;
            Vt[g * 2][j] = src[0];
            Vt[g * 2 + 1][j] = src[1];
        }
        __syncthreads();

        // S = Q @ K^T  (scaled)
        float s[2][8][4];
        #pragma unroll
        for (int mi = 0; mi < 2; mi++)
            #pragma unroll
            for (int ni = 0; ni < 8; ni++)
                #pragma unroll
                for (int t = 0; t < 4; t++) s[mi][ni][t] = 0.f;
        #pragma unroll
        for (int kk = 0; kk < 4; kk++) {
            u32 bfr[8][2];
            #pragma unroll
            for (int ni = 0; ni < 8; ni++)
                ldsm_x2(bfr[ni], &Ks[ni * 8 + brow][kk * 16 + bkk]);
            #pragma unroll
            for (int mi = 0; mi < 2; mi++)
                #pragma unroll
                for (int ni = 0; ni < 8; ni++)
                    mma_bf16(s[mi][ni], qa[mi][kk], bfr[ni]);
        }

        // online softmax per mi (rows gp and gp+8)
        #pragma unroll
        for (int mi = 0; mi < 2; mi++) {
            float mx0 = -1e30f, mx1 = -1e30f;
            #pragma unroll
            for (int ni = 0; ni < 8; ni++) {
                #pragma unroll
                for (int t = 0; t < 4; t++) s[mi][ni][t] *= ATTN_SCALE;
                mx0 = fmaxf(mx0, fmaxf(s[mi][ni][0], s[mi][ni][1]));
                mx1 = fmaxf(mx1, fmaxf(s[mi][ni][2], s[mi][ni][3]));
            }
            mx0 = fmaxf(mx0, __shfl_xor_sync(0xffffffffu, mx0, 1));
            mx0 = fmaxf(mx0, __shfl_xor_sync(0xffffffffu, mx0, 2));
            mx1 = fmaxf(mx1, __shfl_xor_sync(0xffffffffu, mx1, 1));
            mx1 = fmaxf(mx1, __shfl_xor_sync(0xffffffffu, mx1, 2));
            float mn0 = fmaxf(mrow[mi][0], mx0);
            float mn1 = fmaxf(mrow[mi][1], mx1);
            float a0 = __expf(mrow[mi][0] - mn0);
            float a1 = __expf(mrow[mi][1] - mn1);
            float ps0 = 0.f, ps1 = 0.f;
            #pragma unroll
            for (int ni = 0; ni < 8; ni++) {
                s[mi][ni][0] = __expf(s[mi][ni][0] - mn0);
                s[mi][ni][1] = __expf(s[mi][ni][1] - mn0);
                s[mi][ni][2] = __expf(s[mi][ni][2] - mn1);
                s[mi][ni][3] = __expf(s[mi][ni][3] - mn1);
                ps0 += s[mi][ni][0] + s[mi][ni][1];
                ps1 += s[mi][ni][2] + s[mi][ni][3];
            }
            ps0 += __shfl_xor_sync(0xffffffffu, ps0, 1);
            ps0 += __shfl_xor_sync(0xffffffffu, ps0, 2);
            ps1 += __shfl_xor_sync(0xffffffffu, ps1, 1);
            ps1 += __shfl_xor_sync(0xffffffffu, ps1, 2);
            lrow[mi][0] = lrow[mi][0] * a0 + ps0;
            lrow[mi][1] = lrow[mi][1] * a1 + ps1;
            mrow[mi][0] = mn0;
            mrow[mi][1] = mn1;
            #pragma unroll
            for (int nd = 0; nd < 8; nd++) {
                o[mi][nd][0] *= a0; o[mi][nd][1] *= a0;
                o[mi][nd][2] *= a1; o[mi][nd][3] *= a1;
            }
        }

        // O += P @ V   (C-fragment of S reused as A-fragment)
        #pragma unroll
        for (int kk = 0; kk < 4; kk++) {
            u32 pa[2][4];
            #pragma unroll
            for (int mi = 0; mi < 2; mi++) {
                pa[mi][0] = packbf2(s[mi][2 * kk][0],     s[mi][2 * kk][1]);
                pa[mi][1] = packbf2(s[mi][2 * kk][2],     s[mi][2 * kk][3]);
                pa[mi][2] = packbf2(s[mi][2 * kk + 1][0], s[mi][2 * kk + 1][1]);
                pa[mi][3] = packbf2(s[mi][2 * kk + 1][2], s[mi][2 * kk + 1][3]);
            }
            u32 vfr[8][2];
            #pragma unroll
            for (int nd = 0; nd < 8; nd++)
                ldsm_x2(vfr[nd], &Vt[nd * 8 + brow][kk * 16 + bkk]);
            #pragma unroll
            for (int mi = 0; mi < 2; mi++)
                #pragma unroll
                for (int nd = 0; nd < 8; nd++)
                    mma_bf16(o[mi][nd], pa[mi], vfr[nd]);
        }
    }

    // normalize + store bf16 to token-major [token][h*64+d]
    #pragma unroll
    for (int mi = 0; mi < 2; mi++) {
        float inv0 = 1.0f / lrow[mi][0];
        float inv1 = 1.0f / lrow[mi][1];
        int r0 = wid * 32 + mi * 16 + gp;
        #pragma unroll
        for (int nd = 0; nd < 8; nd++) {
            int col = h * DD + nd * 8 + tin * 2;
            __nv_bfloat162 p0, p1;
            p0.x = __float2bfloat16(o[mi][nd][0] * inv0);
            p0.y = __float2bfloat16(o[mi][nd][1] * inv0);
            p1.x = __float2bfloat16(o[mi][nd][2] * inv1);
            p1.y = __float2bfloat16(o[mi][nd][3] * inv1);
            *(__nv_bfloat162*)&o_out[(tok0 + r0) * CC + col] = p0;
            *(__nv_bfloat162*)&o_out[(tok0 + r0 + 8) * CC + col] = p1;
        }
    }
}

// ---------------------------------------------------------------------------
extern "C" void kernel_launch(void* const* d_in, const int* in_sizes, int n_in,
                              void* d_out, int out_size)
{
    const float* x     = (const float*)d_in[0];
    const float* Wqkv  = (const float*)d_in[1];
    const float* Wproj = (const float*)d_in[2];
    const float* bproj = (const float*)d_in[3];
    const float* ln1g  = (const float*)d_in[4];
    const float* ln1b  = (const float*)d_in[5];
    const float* ln2g  = (const float*)d_in[6];
    const float* ln2b  = (const float*)d_in[7];
    const float* Wm1   = (const float*)d_in[8];
    const float* bm1   = (const float*)d_in[9];
    const float* Wm2   = (const float*)d_in[10];
    const float* bm2   = (const float*)d_in[11];
    float* out = (float*)d_out;

    float *p_xseq, *p_x2, *p_y;
    bf16 *p_qkvb, *p_hb, *p_ab, *p_mb, *p_wq, *p_wp, *p_w1, *p_w2;
    cudaGetSymbolAddress((void**)&p_xseq, g_xseq);
    cudaGetSymbolAddress((void**)&p_x2,   g_x2);
    cudaGetSymbolAddress((void**)&p_y,    g_y);
    cudaGetSymbolAddress((void**)&p_qkvb, g_qkvb);
    cudaGetSymbolAddress((void**)&p_hb,   g_hb);
    cudaGetSymbolAddress((void**)&p_ab,   g_ab);
    cudaGetSymbolAddress((void**)&p_mb,   g_mb);
    cudaGetSymbolAddress((void**)&p_wq,   g_wq);
    cudaGetSymbolAddress((void**)&p_wp,   g_wp);
    cudaGetSymbolAddress((void**)&p_w1,   g_w1);
    cudaGetSymbolAddress((void**)&p_w2,   g_w2);

    dim3 tb(32, 8);
    // weight conversions (cheap)
    k_f2b<<<(QKV * CC + 255) / 256, 256>>>(Wqkv, p_wq, QKV * CC);
    k_f2b<<<(CC * CC + 255) / 256, 256>>>(Wproj, p_wp, CC * CC);
    k_f2b<<<(HID * CC + 255) / 256, 256>>>(Wm1, p_w1, HID * CC);
    k_f2b<<<(CC * HID + 255) / 256, 256>>>(Wm2, p_w2, CC * HID);
    // 1) transpose to token-major
    k_transpose_in<<<dim3(PP / 32, CC / 32, BB * NN), tb>>>(x, p_xseq);
    // 2) LN1 -> bf16
    k_layernorm<<<SS / 8, tb>>>(p_xseq, ln1g, ln1b, p_hb);
    // 3) qkv = h @ Wqkv^T (tensor cores, bf16 out)
    k_gemm_tc<0, 1> <<<dim3(QKV / 128, SS / 128), 256>>>(p_hb, p_wq, (const float*)0, (const float*)0, (float*)0, p_qkvb, CC, QKV);
    // 4) tensor-core flash attention -> bf16
    k_attn_tc<<<dim3(BB * NN, HH), 256>>>(p_qkvb, p_ab);
    // 5) proj + bias + residual(x_seq) -> fp32 x2
    k_gemm_tc<3, 0> <<<dim3(CC / 128, SS / 128), 256>>>(p_ab, p_wp, bproj, p_xseq, p_x2, (bf16*)0, CC, CC);
    // 6) LN2 -> bf16
    k_layernorm<<<SS / 8, tb>>>(p_x2, ln2g, ln2b, p_hb);
    // 7) mlp1 + bias + gelu -> bf16
    k_gemm_tc<2, 1> <<<dim3(HID / 128, SS / 128), 256>>>(p_hb, p_w1, bm1, (const float*)0, (float*)0, p_mb, CC, HID);
    // 8) mlp2 + bias + residual(x2) -> fp32 y
    k_gemm_tc<3, 0> <<<dim3(CC / 128, SS / 128), 256>>>(p_mb, p_w2, bm2, p_x2, p_y, (bf16*)0, HID, CC);
    // 9) transpose back
    k_transpose_out<<<dim3(PP / 32, CC / 32, BB * NN), tb>>>(p_y, out);
}

// round 8
// speedup vs baseline: 5.2764x; 1.0721x over previous
#include <cuda_runtime.h>
#include <cuda_bf16.h>
#include <math.h>
#include <stdint.h>

// Problem constants
#define BB   8
#define CC   256
#define NN   64
#define PP   256
#define SS   (BB * NN * PP)     // 131072 tokens
#define HH   4
#define DD   64
#define HID  512
#define QKV  768
#define ATTN_SCALE 0.125f
#define LN_EPS 1e-5f

typedef __nv_bfloat16 bf16;
typedef unsigned int u32;

// Scratch (static __device__ arrays: allocation-free per harness rules)
__device__ float g_xseq[(size_t)SS * CC];   // transposed input (shortcut 1), fp32
__device__ float g_x2  [(size_t)SS * CC];   // residual after attention, fp32
__device__ bf16  g_qkvb[(size_t)SS * QKV];  // qkv projections, bf16
__device__ bf16  g_hb  [(size_t)SS * CC];   // LN outputs (bf16 GEMM input)
__device__ bf16  g_ab  [(size_t)SS * CC];   // attn out (bf16 GEMM input)
__device__ bf16  g_mb  [(size_t)SS * HID];  // mlp hidden (bf16 GEMM input)
__device__ bf16  g_wq  [QKV * CC];          // bf16 weights
__device__ bf16  g_wp  [CC * CC];
__device__ bf16  g_w1  [HID * CC];
__device__ bf16  g_w2  [CC * HID];

// ---------------------------------------------------------------------------
// All four weight conversions in one launch
// ---------------------------------------------------------------------------
__global__ void k_f2b_all(const float* __restrict__ s0, bf16* __restrict__ d0,
                          const float* __restrict__ s1, bf16* __restrict__ d1,
                          const float* __restrict__ s2, bf16* __restrict__ d2,
                          const float* __restrict__ s3, bf16* __restrict__ d3) {
    int i = blockIdx.x * 256 + threadIdx.x;
    if (i < QKV * CC) { d0[i] = __float2bfloat16(s0[i]); return; }
    i -= QKV * CC;
    if (i < CC * CC)  { d1[i] = __float2bfloat16(s1[i]); return; }
    i -= CC * CC;
    if (i < HID * CC) { d2[i] = __float2bfloat16(s2[i]); return; }
    i -= HID * CC;
    d3[i] = __float2bfloat16(s3[i]);
}
#define F2B_TOTAL (QKV * CC + CC * CC + HID * CC + CC * HID)

// ---------------------------------------------------------------------------
// Fused transpose-in + LN1: x[B,C,N,P] -> xseq fp32 (shortcut) + hb bf16 (LN)
// CTA: (p-tile of 32, bn). smem tile [256][33].
// ---------------------------------------------------------------------------
__global__ void k_tln(const float* __restrict__ x, const float* __restrict__ gamma,
                      const float* __restrict__ beta, float* __restrict__ xseq,
                      bf16* __restrict__ hb) {
    __shared__ float tile[256][33];
    int bn = blockIdx.y;
    int p0 = blockIdx.x * 32;
    int b = bn >> 6, n = bn & 63;
    int lane = threadIdx.x, wid = threadIdx.y;

    #pragma unroll
    for (int c = wid; c < 256; c += 8)
        tile[c][lane] = x[(((size_t)b * CC + c) * NN + n) * PP + p0 + lane];
    __syncthreads();

    #pragma unroll
    for (int t = 0; t < 4; t++) {
        int p = wid * 4 + t;
        float vals[8];
        float sum = 0.f, sq = 0.f;
        #pragma unroll
        for (int k = 0; k < 8; k++) {
            float v = tile[lane + k * 32][p];
            vals[k] = v; sum += v; sq += v * v;
        }
        #pragma unroll
        for (int o = 16; o; o >>= 1) {
            sum += __shfl_xor_sync(0xffffffffu, sum, o);
            sq  += __shfl_xor_sync(0xffffffffu, sq,  o);
        }
        float mu  = sum * (1.0f / CC);
        float var = sq * (1.0f / CC) - mu * mu;
        float inv = rsqrtf(var + LN_EPS);
        size_t row = ((size_t)bn * PP + p0 + p) * CC;
        #pragma unroll
        for (int k = 0; k < 8; k++) {
            int c = lane + k * 32;
            xseq[row + c] = vals[k];
            hb[row + c] = __float2bfloat16((vals[k] - mu) * inv * gamma[c] + beta[c]);
        }
    }
}

// ---------------------------------------------------------------------------
// LayerNorm over C=256 -> bf16 output (used for LN2)
// ---------------------------------------------------------------------------
__global__ void k_layernorm(const float* __restrict__ in, const float* __restrict__ gamma,
                            const float* __restrict__ beta, bf16* __restrict__ out) {
    int row = blockIdx.x * 8 + threadIdx.y;
    int lane = threadIdx.x;
    const float* r = in + (size_t)row * CC;
    float vals[8];
    float sum = 0.f, sq = 0.f;
    #pragma unroll
    for (int k = 0; k < 8; k++) {
        float t = r[lane + k * 32];
        vals[k] = t; sum += t; sq += t * t;
    }
    #pragma unroll
    for (int o = 16; o; o >>= 1) {
        sum += __shfl_xor_sync(0xffffffffu, sum, o);
        sq  += __shfl_xor_sync(0xffffffffu, sq,  o);
    }
    float mu  = sum * (1.0f / CC);
    float var = sq * (1.0f / CC) - mu * mu;
    float inv = rsqrtf(var + LN_EPS);
    bf16* w = out + (size_t)row * CC;
    #pragma unroll
    for (int k = 0; k < 8; k++) {
        int c = lane + k * 32;
        w[c] = __float2bfloat16((vals[k] - mu) * inv * gamma[c] + beta[c]);
    }
}

// ---------------------------------------------------------------------------
// MMA helpers
// ---------------------------------------------------------------------------
__device__ __forceinline__ float gelu_exact(float v) {
    return 0.5f * v * (1.0f + erff(v * 0.70710678118654752f));
}

#define ST 40   // GEMM smem row stride in bf16 elems (80B = 5*16B)

__device__ __forceinline__ void ldsm_x4(u32* r, const bf16* p) {
    u32 addr = (u32)__cvta_generic_to_shared((const void*)p);
    asm volatile("ldmatrix.sync.aligned.m8n8.x4.shared.b16 {%0,%1,%2,%3}, [%4];"
                 : "=r"(r[0]), "=r"(r[1]), "=r"(r[2]), "=r"(r[3]) : "r"(addr));
}
__device__ __forceinline__ void ldsm_x2(u32* r, const bf16* p) {
    u32 addr = (u32)__cvta_generic_to_shared((const void*)p);
    asm volatile("ldmatrix.sync.aligned.m8n8.x2.shared.b16 {%0,%1}, [%2];"
                 : "=r"(r[0]), "=r"(r[1]) : "r"(addr));
}
__device__ __forceinline__ void mma_bf16(float* c, const u32* a, const u32* b) {
    asm volatile("mma.sync.aligned.m16n8k16.row.col.f32.bf16.bf16.f32 "
                 "{%0,%1,%2,%3}, {%4,%5,%6,%7}, {%8,%9}, {%0,%1,%2,%3};"
                 : "+f"(c[0]), "+f"(c[1]), "+f"(c[2]), "+f"(c[3])
                 : "r"(a[0]), "r"(a[1]), "r"(a[2]), "r"(a[3]), "r"(b[0]), "r"(b[1]));
}
__device__ __forceinline__ u32 packbf2(float a, float b) {
    __nv_bfloat162 t = __float22bfloat162_rn(make_float2(a, b));
    return *(u32*)&t;
}
__device__ __forceinline__ void cp16(bf16* dst, const bf16* src) {
    u32 d = (u32)__cvta_generic_to_shared((void*)dst);
    asm volatile("cp.async.ca.shared.global [%0], [%1], 16;" :: "r"(d), "l"(src));
}

// ---------------------------------------------------------------------------
// Tensor-core bf16 GEMM with cp.async double buffering.
// out[m,n] = sum_k A[m,k]*W[n,k]  (+epilogue)
// BM=BN=128, BK=32, 256 threads = 8 warps (2x4), each warp 64x32 via m16n8k16.
// EPI: 0=none, 2=bias+gelu, 3=bias+residual, 4=bias+residual+transpose-out.
// OUTBF: 0=float out, 1=bf16 out.
// ---------------------------------------------------------------------------
template<int EPI, int OUTBF>
__global__ __launch_bounds__(256) void k_gemm_tc(
    const bf16* __restrict__ A, const bf16* __restrict__ W,
    const float* __restrict__ bias, const float* __restrict__ res,
    float* __restrict__ outf, bf16* __restrict__ outb, int K, int O)
{
    __shared__ bf16 As[2][128 * ST];
    __shared__ bf16 Bs[2][128 * ST];
    int tid = threadIdx.x;
    int wid = tid >> 5, lane = tid & 31;
    int warp_m = wid >> 2, warp_n = wid & 3;
    int m0 = blockIdx.y * 128, n0 = blockIdx.x * 128;

    float acc[4][4][4];
    #pragma unroll
    for (int i = 0; i < 4; i++)
        #pragma unroll
        for (int j = 0; j < 4; j++)
            #pragma unroll
            for (int t = 0; t < 4; t++) acc[i][j][t] = 0.f;

    int lrw = tid >> 2, lcc = (tid & 3) * 8;

    // prologue: stage 0
    cp16(&As[0][lrw * ST + lcc],        &A[(size_t)(m0 + lrw) * K + lcc]);
    cp16(&As[0][(lrw + 64) * ST + lcc], &A[(size_t)(m0 + 64 + lrw) * K + lcc]);
    cp16(&Bs[0][lrw * ST + lcc],        &W[(size_t)(n0 + lrw) * K + lcc]);
    cp16(&Bs[0][(lrw + 64) * ST + lcc], &W[(size_t)(n0 + 64 + lrw) * K + lcc]);
    asm volatile("cp.async.commit_group;");

    int KT = K >> 5;
    int arow = (lane & 15), akk = (lane >> 4) * 8;
    int brow = (lane & 7),  bkk = ((lane >> 3) & 1) * 8;

    for (int kt = 0; kt < KT; kt++) {
        if (kt + 1 < KT) {
            int kb = (kt + 1) * 32;
            int nb = (kt + 1) & 1;
            cp16(&As[nb][lrw * ST + lcc],        &A[(size_t)(m0 + lrw) * K + kb + lcc]);
            cp16(&As[nb][(lrw + 64) * ST + lcc], &A[(size_t)(m0 + 64 + lrw) * K + kb + lcc]);
            cp16(&Bs[nb][lrw * ST + lcc],        &W[(size_t)(n0 + lrw) * K + kb + lcc]);
            cp16(&Bs[nb][(lrw + 64) * ST + lcc], &W[(size_t)(n0 + 64 + lrw) * K + kb + lcc]);
            asm volatile("cp.async.commit_group;");
            asm volatile("cp.async.wait_group 1;");
        } else {
            asm volatile("cp.async.wait_group 0;");
        }
        __syncthreads();
        int bf = kt & 1;
        #pragma unroll
        for (int kk = 0; kk < 32; kk += 16) {
            u32 afr[4][4], bfr[4][2];
            #pragma unroll
            for (int mi = 0; mi < 4; mi++)
                ldsm_x4(afr[mi], &As[bf][(warp_m * 64 + mi * 16 + arow) * ST + kk + akk]);
            #pragma unroll
            for (int ni = 0; ni < 4; ni++)
                ldsm_x2(bfr[ni], &Bs[bf][(warp_n * 32 + ni * 8 + brow) * ST + kk + bkk]);
            #pragma unroll
            for (int mi = 0; mi < 4; mi++)
                #pragma unroll
                for (int ni = 0; ni < 4; ni++)
                    mma_bf16(acc[mi][ni], afr[mi], bfr[ni]);
        }
        __syncthreads();
    }

    int gp = lane >> 2, tin = lane & 3;
    #pragma unroll
    for (int ni = 0; ni < 4; ni++) {
        int col = n0 + warp_n * 32 + ni * 8 + tin * 2;
        float bx = 0.f, by = 0.f;
        if (EPI >= 2) { float2 b2 = *(const float2*)&bias[col]; bx = b2.x; by = b2.y; }
        #pragma unroll
        for (int mi = 0; mi < 4; mi++) {
            int row = m0 + warp_m * 64 + mi * 16 + gp;
            #pragma unroll
            for (int half = 0; half < 2; half++) {
                int r = row + half * 8;
                float vx = acc[mi][ni][half * 2 + 0] + bx;
                float vy = acc[mi][ni][half * 2 + 1] + by;
                if (EPI == 2) { vx = gelu_exact(vx); vy = gelu_exact(vy); }
                if (EPI == 3 || EPI == 4) {
                    float2 rr = *(const float2*)&res[(size_t)r * O + col];
                    vx += rr.x; vy += rr.y;
                }
                if (EPI == 4) {
                    // direct store to out[B,C,N,P]
                    int bn = r >> 8, p = r & 255;
                    int b = bn >> 6, n = bn & 63;
                    outf[(((size_t)b * CC + col) * NN + n) * PP + p] = vx;
                    outf[(((size_t)b * CC + col + 1) * NN + n) * PP + p] = vy;
                } else if (OUTBF) {
                    __nv_bfloat162 p2;
                    p2.x = __float2bfloat16(vx); p2.y = __float2bfloat16(vy);
                    *(__nv_bfloat162*)&outb[(size_t)r * O + col] = p2;
                } else {
                    *(float2*)&outf[(size_t)r * O + col] = make_float2(vx, vy);
                }
            }
        }
    }
}

// ---------------------------------------------------------------------------
// Tensor-core flash attention: one CTA per (seq, head). 8 warps x 32 q-rows.
// ---------------------------------------------------------------------------
__global__ __launch_bounds__(256) void k_attn_tc(const bf16* __restrict__ qkv,
                                                 bf16* __restrict__ o_out)
{
    __shared__ bf16 Ks[64][72];   // [key][d]
    __shared__ bf16 Vt[64][72];   // [d][key]

    int sq = blockIdx.x, h = blockIdx.y;
    int tid = threadIdx.x, wid = tid >> 5, lane = tid & 31;
    int gp = lane >> 2, tin = lane & 3;
    int brow = lane & 7, bkk = ((lane >> 3) & 1) * 8;
    const size_t tok0 = (size_t)sq * PP;
    const bf16* qb = qkv + tok0 * QKV + h * DD;
    const bf16* kb = qkv + tok0 * QKV + 256 + h * DD;
    const bf16* vb = qkv + tok0 * QKV + 512 + h * DD;

    u32 qa[2][4][4];
    #pragma unroll
    for (int mi = 0; mi < 2; mi++) {
        int r0 = wid * 32 + mi * 16 + gp;
        #pragma unroll
        for (int kk = 0; kk < 4; kk++) {
            const bf16* p0 = qb + (size_t)r0 * QKV + kk * 16 + tin * 2;
            const bf16* p1 = qb + (size_t)(r0 + 8) * QKV + kk * 16 + tin * 2;
            qa[mi][kk][0] = *(const u32*)p0;
            qa[mi][kk][1] = *(const u32*)p1;
            qa[mi][kk][2] = *(const u32*)(p0 + 8);
            qa[mi][kk][3] = *(const u32*)(p1 + 8);
        }
    }

    float o[2][8][4];
    #pragma unroll
    for (int mi = 0; mi < 2; mi++)
        #pragma unroll
        for (int nd = 0; nd < 8; nd++)
            #pragma unroll
            for (int t = 0; t < 4; t++) o[mi][nd][t] = 0.f;
    float mrow[2][2] = {{-1e30f, -1e30f}, {-1e30f, -1e30f}};
    float lrow[2][2] = {{0.f, 0.f}, {0.f, 0.f}};

    for (int c0 = 0; c0 < PP; c0 += 64) {
        __syncthreads();
        for (int i = tid; i < 64 * 8; i += 256) {
            int j = i >> 3, q8 = i & 7;
            *(uint4*)&Ks[j][q8 * 8] = *(const uint4*)(kb + (size_t)(c0 + j) * QKV + q8 * 8);
        }
        for (int i = tid; i < 64 * 32; i += 256) {
            int j = i >> 5, g = i & 31;
            const bf16* src = vb + (size_t)(c0 + j) * QKV + g * 2;
            Vt[g * 2][j] = src[0];
            Vt[g * 2 + 1][j] = src[1];
        }
        __syncthreads();

        float s[2][8][4];
        #pragma unroll
        for (int mi = 0; mi < 2; mi++)
            #pragma unroll
            for (int ni = 0; ni < 8; ni++)
                #pragma unroll
                for (int t = 0; t < 4; t++) s[mi][ni][t] = 0.f;
        #pragma unroll
        for (int kk = 0; kk < 4; kk++) {
            u32 bfr[8][2];
            #pragma unroll
            for (int ni = 0; ni < 8; ni++)
                ldsm_x2(bfr[ni], &Ks[ni * 8 + brow][kk * 16 + bkk]);
            #pragma unroll
            for (int mi = 0; mi < 2; mi++)
                #pragma unroll
                for (int ni = 0; ni < 8; ni++)
                    mma_bf16(s[mi][ni], qa[mi][kk], bfr[ni]);
        }

        #pragma unroll
        for (int mi = 0; mi < 2; mi++) {
            float mx0 = -1e30f, mx1 = -1e30f;
            #pragma unroll
            for (int ni = 0; ni < 8; ni++) {
                #pragma unroll
                for (int t = 0; t < 4; t++) s[mi][ni][t] *= ATTN_SCALE;
                mx0 = fmaxf(mx0, fmaxf(s[mi][ni][0], s[mi][ni][1]));
                mx1 = fmaxf(mx1, fmaxf(s[mi][ni][2], s[mi][ni][3]));
            }
            mx0 = fmaxf(mx0, __shfl_xor_sync(0xffffffffu, mx0, 1));
            mx0 = fmaxf(mx0, __shfl_xor_sync(0xffffffffu, mx0, 2));
            mx1 = fmaxf(mx1, __shfl_xor_sync(0xffffffffu, mx1, 1));
            mx1 = fmaxf(mx1, __shfl_xor_sync(0xffffffffu, mx1, 2));
            float mn0 = fmaxf(mrow[mi][0], mx0);
            float mn1 = fmaxf(mrow[mi][1], mx1);
            float a0 = __expf(mrow[mi][0] - mn0);
            float a1 = __expf(mrow[mi][1] - mn1);
            float ps0 = 0.f, ps1 = 0.f;
            #pragma unroll
            for (int ni = 0; ni < 8; ni++) {
                s[mi][ni][0] = __expf(s[mi][ni][0] - mn0);
                s[mi][ni][1] = __expf(s[mi][ni][1] - mn0);
                s[mi][ni][2] = __expf(s[mi][ni][2] - mn1);
                s[mi][ni][3] = __expf(s[mi][ni][3] - mn1);
                ps0 += s[mi][ni][0] + s[mi][ni][1];
                ps1 += s[mi][ni][2] + s[mi][ni][3];
            }
            ps0 += __shfl_xor_sync(0xffffffffu, ps0, 1);
            ps0 += __shfl_xor_sync(0xffffffffu, ps0, 2);
            ps1 += __shfl_xor_sync(0xffffffffu, ps1, 1);
            ps1 += __shfl_xor_sync(0xffffffffu, ps1, 2);
            lrow[mi][0] = lrow[mi][0] * a0 + ps0;
            lrow[mi][1] = lrow[mi][1] * a1 + ps1;
            mrow[mi][0] = mn0;
            mrow[mi][1] = mn1;
            #pragma unroll
            for (int nd = 0; nd < 8; nd++) {
                o[mi][nd][0] *= a0; o[mi][nd][1] *= a0;
                o[mi][nd][2] *= a1; o[mi][nd][3] *= a1;
            }
        }

        #pragma unroll
        for (int kk = 0; kk < 4; kk++) {
            u32 pa[2][4];
            #pragma unroll
            for (int mi = 0; mi < 2; mi++) {
                pa[mi][0] = packbf2(s[mi][2 * kk][0],     s[mi][2 * kk][1]);
                pa[mi][1] = packbf2(s[mi][2 * kk][2],     s[mi][2 * kk][3]);
                pa[mi][2] = packbf2(s[mi][2 * kk + 1][0], s[mi][2 * kk + 1][1]);
                pa[mi][3] = packbf2(s[mi][2 * kk + 1][2], s[mi][2 * kk + 1][3]);
            }
            u32 vfr[8][2];
            #pragma unroll
            for (int nd = 0; nd < 8; nd++)
                ldsm_x2(vfr[nd], &Vt[nd * 8 + brow][kk * 16 + bkk]);
            #pragma unroll
            for (int mi = 0; mi < 2; mi++)
                #pragma unroll
                for (int nd = 0; nd < 8; nd++)
                    mma_bf16(o[mi][nd], pa[mi], vfr[nd]);
        }
    }

    #pragma unroll
    for (int mi = 0; mi < 2; mi++) {
        float inv0 = 1.0f / lrow[mi][0];
        float inv1 = 1.0f / lrow[mi][1];
        int r0 = wid * 32 + mi * 16 + gp;
        #pragma unroll
        for (int nd = 0; nd < 8; nd++) {
            int col = h * DD + nd * 8 + tin * 2;
            __nv_bfloat162 p0, p1;
            p0.x = __float2bfloat16(o[mi][nd][0] * inv0);
            p0.y = __float2bfloat16(o[mi][nd][1] * inv0);
            p1.x = __float2bfloat16(o[mi][nd][2] * inv1);
            p1.y = __float2bfloat16(o[mi][nd][3] * inv1);
            *(__nv_bfloat162*)&o_out[(tok0 + r0) * CC + col] = p0;
            *(__nv_bfloat162*)&o_out[(tok0 + r0 + 8) * CC + col] = p1;
        }
    }
}

// ---------------------------------------------------------------------------
extern "C" void kernel_launch(void* const* d_in, const int* in_sizes, int n_in,
                              void* d_out, int out_size)
{
    const float* x     = (const float*)d_in[0];
    const float* Wqkv  = (const float*)d_in[1];
    const float* Wproj = (const float*)d_in[2];
    const float* bproj = (const float*)d_in[3];
    const float* ln1g  = (const float*)d_in[4];
    const float* ln1b  = (const float*)d_in[5];
    const float* ln2g  = (const float*)d_in[6];
    const float* ln2b  = (const float*)d_in[7];
    const float* Wm1   = (const float*)d_in[8];
    const float* bm1   = (const float*)d_in[9];
    const float* Wm2   = (const float*)d_in[10];
    const float* bm2   = (const float*)d_in[11];
    float* out = (float*)d_out;

    float *p_xseq, *p_x2;
    bf16 *p_qkvb, *p_hb, *p_ab, *p_mb, *p_wq, *p_wp, *p_w1, *p_w2;
    cudaGetSymbolAddress((void**)&p_xseq, g_xseq);
    cudaGetSymbolAddress((void**)&p_x2,   g_x2);
    cudaGetSymbolAddress((void**)&p_qkvb, g_qkvb);
    cudaGetSymbolAddress((void**)&p_hb,   g_hb);
    cudaGetSymbolAddress((void**)&p_ab,   g_ab);
    cudaGetSymbolAddress((void**)&p_mb,   g_mb);
    cudaGetSymbolAddress((void**)&p_wq,   g_wq);
    cudaGetSymbolAddress((void**)&p_wp,   g_wp);
    cudaGetSymbolAddress((void**)&p_w1,   g_w1);
    cudaGetSymbolAddress((void**)&p_w2,   g_w2);

    dim3 tb(32, 8);
    // weight conversions (one launch)
    k_f2b_all<<<(F2B_TOTAL + 255) / 256, 256>>>(Wqkv, p_wq, Wproj, p_wp, Wm1, p_w1, Wm2, p_w2);
    // 1) fused transpose-in + LN1 -> xseq fp32 + hb bf16
    k_tln<<<dim3(PP / 32, BB * NN), tb>>>(x, ln1g, ln1b, p_xseq, p_hb);
    // 2) qkv = h @ Wqkv^T (tensor cores, bf16 out)
    k_gemm_tc<0, 1> <<<dim3(QKV / 128, SS / 128), 256>>>(p_hb, p_wq, (const float*)0, (const float*)0, (float*)0, p_qkvb, CC, QKV);
    // 3) tensor-core flash attention -> bf16
    k_attn_tc<<<dim3(BB * NN, HH), 256>>>(p_qkvb, p_ab);
    // 4) proj + bias + residual(x_seq) -> fp32 x2
    k_gemm_tc<3, 0> <<<dim3(CC / 128, SS / 128), 256>>>(p_ab, p_wp, bproj, p_xseq, p_x2, (bf16*)0, CC, CC);
    // 5) LN2 -> bf16
    k_layernorm<<<SS / 8, tb>>>(p_x2, ln2g, ln2b, p_hb);
    // 6) mlp1 + bias + gelu -> bf16
    k_gemm_tc<2, 1> <<<dim3(HID / 128, SS / 128), 256>>>(p_hb, p_w1, bm1, (const float*)0, (float*)0, p_mb, CC, HID);
    // 7) mlp2 + bias + residual(x2) + fused transpose-out -> out[B,C,N,P]
    k_gemm_tc<4, 0> <<<dim3(CC / 128, SS / 128), 256>>>(p_mb, p_w2, bm2, p_x2, out, (bf16*)0, HID, CC);
}

// round 12
// speedup vs baseline: 6.0756x; 1.1515x over previous
#include <cuda_runtime.h>
#include <cuda_bf16.h>
#include <math.h>
#include <stdint.h>

// Problem constants
#define BB   8
#define CC   256
#define NN   64
#define PP   256
#define SS   (BB * NN * PP)     // 131072 tokens
#define HH   4
#define DD   64
#define HID  512
#define QKV  768
#define ATTN_SCALE 0.125f
#define LN_EPS 1e-5f

typedef __nv_bfloat16 bf16;
typedef unsigned int u32;

// Scratch (static __device__ arrays: allocation-free per harness rules)
__device__ float g_xseq[(size_t)SS * CC];   // transposed input (shortcut 1), fp32
__device__ float g_x2  [(size_t)SS * CC];   // residual after attention, fp32
__device__ bf16  g_qkvb[(size_t)SS * QKV];  // qkv projections, bf16
__device__ bf16  g_hb  [(size_t)SS * CC];   // LN outputs (bf16 GEMM input)
__device__ bf16  g_ab  [(size_t)SS * CC];   // attn out (bf16 GEMM input)
__device__ bf16  g_mb  [(size_t)SS * HID];  // mlp hidden (bf16 GEMM input)
__device__ bf16  g_wq  [QKV * CC];          // bf16 weights
__device__ bf16  g_wp  [CC * CC];
__device__ bf16  g_w1  [HID * CC];
__device__ bf16  g_w2  [CC * HID];

// ---------------------------------------------------------------------------
// All four weight conversions in one launch
// ---------------------------------------------------------------------------
__global__ void k_f2b_all(const float* __restrict__ s0, bf16* __restrict__ d0,
                          const float* __restrict__ s1, bf16* __restrict__ d1,
                          const float* __restrict__ s2, bf16* __restrict__ d2,
                          const float* __restrict__ s3, bf16* __restrict__ d3) {
    int i = blockIdx.x * 256 + threadIdx.x;
    if (i < QKV * CC) { d0[i] = __float2bfloat16(s0[i]); return; }
    i -= QKV * CC;
    if (i < CC * CC)  { d1[i] = __float2bfloat16(s1[i]); return; }
    i -= CC * CC;
    if (i < HID * CC) { d2[i] = __float2bfloat16(s2[i]); return; }
    i -= HID * CC;
    d3[i] = __float2bfloat16(s3[i]);
}
#define F2B_TOTAL (QKV * CC + CC * CC + HID * CC + CC * HID)

// ---------------------------------------------------------------------------
// Fused transpose-in + LN1: x[B,C,N,P] -> xseq fp32 (shortcut) + hb bf16 (LN)
// ---------------------------------------------------------------------------
__global__ void k_tln(const float* __restrict__ x, const float* __restrict__ gamma,
                      const float* __restrict__ beta, float* __restrict__ xseq,
                      bf16* __restrict__ hb) {
    __shared__ float tile[256][33];
    int bn = blockIdx.y;
    int p0 = blockIdx.x * 32;
    int b = bn >> 6, n = bn & 63;
    int lane = threadIdx.x, wid = threadIdx.y;

    #pragma unroll
    for (int c = wid; c < 256; c += 8)
        tile[c][lane] = x[(((size_t)b * CC + c) * NN + n) * PP + p0 + lane];
    __syncthreads();

    #pragma unroll
    for (int t = 0; t < 4; t++) {
        int p = wid * 4 + t;
        float vals[8];
        float sum = 0.f, sq = 0.f;
        #pragma unroll
        for (int k = 0; k < 8; k++) {
            float v = tile[lane + k * 32][p];
            vals[k] = v; sum += v; sq += v * v;
        }
        #pragma unroll
        for (int o = 16; o; o >>= 1) {
            sum += __shfl_xor_sync(0xffffffffu, sum, o);
            sq  += __shfl_xor_sync(0xffffffffu, sq,  o);
        }
        float mu  = sum * (1.0f / CC);
        float var = sq * (1.0f / CC) - mu * mu;
        float inv = rsqrtf(var + LN_EPS);
        size_t row = ((size_t)bn * PP + p0 + p) * CC;
        #pragma unroll
        for (int k = 0; k < 8; k++) {
            int c = lane + k * 32;
            xseq[row + c] = vals[k];
            hb[row + c] = __float2bfloat16((vals[k] - mu) * inv * gamma[c] + beta[c]);
        }
    }
}

// ---------------------------------------------------------------------------
// LayerNorm over C=256 -> bf16 output (used for LN2)
// ---------------------------------------------------------------------------
__global__ void k_layernorm(const float* __restrict__ in, const float* __restrict__ gamma,
                            const float* __restrict__ beta, bf16* __restrict__ out) {
    int row = blockIdx.x * 8 + threadIdx.y;
    int lane = threadIdx.x;
    const float* r = in + (size_t)row * CC;
    float vals[8];
    float sum = 0.f, sq = 0.f;
    #pragma unroll
    for (int k = 0; k < 8; k++) {
        float t = r[lane + k * 32];
        vals[k] = t; sum += t; sq += t * t;
    }
    #pragma unroll
    for (int o = 16; o; o >>= 1) {
        sum += __shfl_xor_sync(0xffffffffu, sum, o);
        sq  += __shfl_xor_sync(0xffffffffu, sq,  o);
    }
    float mu  = sum * (1.0f / CC);
    float var = sq * (1.0f / CC) - mu * mu;
    float inv = rsqrtf(var + LN_EPS);
    bf16* w = out + (size_t)row * CC;
    #pragma unroll
    for (int k = 0; k < 8; k++) {
        int c = lane + k * 32;
        w[c] = __float2bfloat16((vals[k] - mu) * inv * gamma[c] + beta[c]);
    }
}

// ---------------------------------------------------------------------------
// MMA helpers
// ---------------------------------------------------------------------------
__device__ __forceinline__ float gelu_exact(float v) {
    return 0.5f * v * (1.0f + erff(v * 0.70710678118654752f));
}

#define ST 40   // GEMM smem row stride in bf16 elems (80B = 5*16B)

__device__ __forceinline__ void ldsm_x4(u32* r, const bf16* p) {
    u32 addr = (u32)__cvta_generic_to_shared((const void*)p);
    asm volatile("ldmatrix.sync.aligned.m8n8.x4.shared.b16 {%0,%1,%2,%3}, [%4];"
                 : "=r"(r[0]), "=r"(r[1]), "=r"(r[2]), "=r"(r[3]) : "r"(addr));
}
__device__ __forceinline__ void ldsm_x2(u32* r, const bf16* p) {
    u32 addr = (u32)__cvta_generic_to_shared((const void*)p);
    asm volatile("ldmatrix.sync.aligned.m8n8.x2.shared.b16 {%0,%1}, [%2];"
                 : "=r"(r[0]), "=r"(r[1]) : "r"(addr));
}
__device__ __forceinline__ void ldsm_x2_trans(u32* r, const bf16* p) {
    u32 addr = (u32)__cvta_generic_to_shared((const void*)p);
    asm volatile("ldmatrix.sync.aligned.m8n8.x2.trans.shared.b16 {%0,%1}, [%2];"
                 : "=r"(r[0]), "=r"(r[1]) : "r"(addr));
}
__device__ __forceinline__ void mma_bf16(float* c, const u32* a, const u32* b) {
    asm volatile("mma.sync.aligned.m16n8k16.row.col.f32.bf16.bf16.f32 "
                 "{%0,%1,%2,%3}, {%4,%5,%6,%7}, {%8,%9}, {%0,%1,%2,%3};"
                 : "+f"(c[0]), "+f"(c[1]), "+f"(c[2]), "+f"(c[3])
                 : "r"(a[0]), "r"(a[1]), "r"(a[2]), "r"(a[3]), "r"(b[0]), "r"(b[1]));
}
__device__ __forceinline__ u32 packbf2(float a, float b) {
    __nv_bfloat162 t = __float22bfloat162_rn(make_float2(a, b));
    return *(u32*)&t;
}
__device__ __forceinline__ void cp16(bf16* dst, const bf16* src) {
    u32 d = (u32)__cvta_generic_to_shared((void*)dst);
    asm volatile("cp.async.ca.shared.global [%0], [%1], 16;" :: "r"(d), "l"(src));
}

// ---------------------------------------------------------------------------
// Tensor-core bf16 GEMM with cp.async double buffering (unchanged from R8).
// ---------------------------------------------------------------------------
template<int EPI, int OUTBF>
__global__ __launch_bounds__(256) void k_gemm_tc(
    const bf16* __restrict__ A, const bf16* __restrict__ W,
    const float* __restrict__ bias, const float* __restrict__ res,
    float* __restrict__ outf, bf16* __restrict__ outb, int K, int O)
{
    __shared__ bf16 As[2][128 * ST];
    __shared__ bf16 Bs[2][128 * ST];
    int tid = threadIdx.x;
    int wid = tid >> 5, lane = tid & 31;
    int warp_m = wid >> 2, warp_n = wid & 3;
    int m0 = blockIdx.y * 128, n0 = blockIdx.x * 128;

    float acc[4][4][4];
    #pragma unroll
    for (int i = 0; i < 4; i++)
        #pragma unroll
        for (int j = 0; j < 4; j++)
            #pragma unroll
            for (int t = 0; t < 4; t++) acc[i][j][t] = 0.f;

    int lrw = tid >> 2, lcc = (tid & 3) * 8;

    cp16(&As[0][lrw * ST + lcc],        &A[(size_t)(m0 + lrw) * K + lcc]);
    cp16(&As[0][(lrw + 64) * ST + lcc], &A[(size_t)(m0 + 64 + lrw) * K + lcc]);
    cp16(&Bs[0][lrw * ST + lcc],        &W[(size_t)(n0 + lrw) * K + lcc]);
    cp16(&Bs[0][(lrw + 64) * ST + lcc], &W[(size_t)(n0 + 64 + lrw) * K + lcc]);
    asm volatile("cp.async.commit_group;");

    int KT = K >> 5;
    int arow = (lane & 15), akk = (lane >> 4) * 8;
    int brow = (lane & 7),  bkk = ((lane >> 3) & 1) * 8;

    for (int kt = 0; kt < KT; kt++) {
        if (kt + 1 < KT) {
            int kb = (kt + 1) * 32;
            int nb = (kt + 1) & 1;
            cp16(&As[nb][lrw * ST + lcc],        &A[(size_t)(m0 + lrw) * K + kb + lcc]);
            cp16(&As[nb][(lrw + 64) * ST + lcc], &A[(size_t)(m0 + 64 + lrw) * K + kb + lcc]);
            cp16(&Bs[nb][lrw * ST + lcc],        &W[(size_t)(n0 + lrw) * K + kb + lcc]);
            cp16(&Bs[nb][(lrw + 64) * ST + lcc], &W[(size_t)(n0 + 64 + lrw) * K + kb + lcc]);
            asm volatile("cp.async.commit_group;");
            asm volatile("cp.async.wait_group 1;");
        } else {
            asm volatile("cp.async.wait_group 0;");
        }
        __syncthreads();
        int bf = kt & 1;
        #pragma unroll
        for (int kk = 0; kk < 32; kk += 16) {
            u32 afr[4][4], bfr[4][2];
            #pragma unroll
            for (int mi = 0; mi < 4; mi++)
                ldsm_x4(afr[mi], &As[bf][(warp_m * 64 + mi * 16 + arow) * ST + kk + akk]);
            #pragma unroll
            for (int ni = 0; ni < 4; ni++)
                ldsm_x2(bfr[ni], &Bs[bf][(warp_n * 32 + ni * 8 + brow) * ST + kk + bkk]);
            #pragma unroll
            for (int mi = 0; mi < 4; mi++)
                #pragma unroll
                for (int ni = 0; ni < 4; ni++)
                    mma_bf16(acc[mi][ni], afr[mi], bfr[ni]);
        }
        __syncthreads();
    }

    int gp = lane >> 2, tin = lane & 3;
    #pragma unroll
    for (int ni = 0; ni < 4; ni++) {
        int col = n0 + warp_n * 32 + ni * 8 + tin * 2;
        float bx = 0.f, by = 0.f;
        if (EPI >= 2) { float2 b2 = *(const float2*)&bias[col]; bx = b2.x; by = b2.y; }
        #pragma unroll
        for (int mi = 0; mi < 4; mi++) {
            int row = m0 + warp_m * 64 + mi * 16 + gp;
            #pragma unroll
            for (int half = 0; half < 2; half++) {
                int r = row + half * 8;
                float vx = acc[mi][ni][half * 2 + 0] + bx;
                float vy = acc[mi][ni][half * 2 + 1] + by;
                if (EPI == 2) { vx = gelu_exact(vx); vy = gelu_exact(vy); }
                if (EPI == 3 || EPI == 4) {
                    float2 rr = *(const float2*)&res[(size_t)r * O + col];
                    vx += rr.x; vy += rr.y;
                }
                if (EPI == 4) {
                    int bn = r >> 8, p = r & 255;
                    int b = bn >> 6, n = bn & 63;
                    outf[(((size_t)b * CC + col) * NN + n) * PP + p] = vx;
                    outf[(((size_t)b * CC + col + 1) * NN + n) * PP + p] = vy;
                } else if (OUTBF) {
                    __nv_bfloat162 p2;
                    p2.x = __float2bfloat16(vx); p2.y = __float2bfloat16(vy);
                    *(__nv_bfloat162*)&outb[(size_t)r * O + col] = p2;
                } else {
                    *(float2*)&outf[(size_t)r * O + col] = make_float2(vx, vy);
                }
            }
        }
    }
}

// ---------------------------------------------------------------------------
// Tensor-core flash attention v2: 128 threads (4 warps x 32 q-rows),
// grid (seq, head, half). K and V both stored [key][d] via cp.async with
// double buffering; V fragments via ldmatrix.trans (no smem transpose).
// ---------------------------------------------------------------------------
__global__ __launch_bounds__(128) void k_attn_tc(const bf16* __restrict__ qkv,
                                                 bf16* __restrict__ o_out)
{
    __shared__ bf16 Ks[2][64][72];   // [buf][key][d], row stride 144B
    __shared__ bf16 Vs[2][64][72];   // [buf][key][d]

    int sq = blockIdx.x, h = blockIdx.y, half = blockIdx.z;
    int tid = threadIdx.x, wid = tid >> 5, lane = tid & 31;
    int gp = lane >> 2, tin = lane & 3;
    int brow = lane & 7, bkk = ((lane >> 3) & 1) * 8;
    int l16 = lane & 15;
    const size_t tok0 = (size_t)sq * PP;
    const bf16* qb = qkv + tok0 * QKV + h * DD;
    const bf16* kb = qkv + tok0 * QKV + 256 + h * DD;
    const bf16* vb = qkv + tok0 * QKV + 512 + h * DD;

    // Q fragments for this warp's 32 rows
    u32 qa[2][4][4];
    #pragma unroll
    for (int mi = 0; mi < 2; mi++) {
        int r0 = half * 128 + wid * 32 + mi * 16 + gp;
        #pragma unroll
        for (int kk = 0; kk < 4; kk++) {
            const bf16* p0 = qb + (size_t)r0 * QKV + kk * 16 + tin * 2;
            const bf16* p1 = qb + (size_t)(r0 + 8) * QKV + kk * 16 + tin * 2;
            qa[mi][kk][0] = *(const u32*)p0;
            qa[mi][kk][1] = *(const u32*)p1;
            qa[mi][kk][2] = *(const u32*)(p0 + 8);
            qa[mi][kk][3] = *(const u32*)(p1 + 8);
        }
    }

    // prologue: chunk 0 loads (K then V), one commit group
    #pragma unroll
    for (int t = 0; t < 4; t++) {
        int idx = t * 128 + tid;
        int j = idx >> 3, q8 = idx & 7;
        cp16(&Ks[0][j][q8 * 8], kb + (size_t)j * QKV + q8 * 8);
        cp16(&Vs[0][j][q8 * 8], vb + (size_t)j * QKV + q8 * 8);
    }
    asm volatile("cp.async.commit_group;");

    float o[2][8][4];
    #pragma unroll
    for (int mi = 0; mi < 2; mi++)
        #pragma unroll
        for (int nd = 0; nd < 8; nd++)
            #pragma unroll
            for (int t = 0; t < 4; t++) o[mi][nd][t] = 0.f;
    float mrow[2][2] = {{-1e30f, -1e30f}, {-1e30f, -1e30f}};
    float lrow[2][2] = {{0.f, 0.f}, {0.f, 0.f}};

    for (int ci = 0; ci < 4; ci++) {
        if (ci + 1 < 4) {
            int c1 = (ci + 1) * 64;
            int nb = (ci + 1) & 1;
            #pragma unroll
            for (int t = 0; t < 4; t++) {
                int idx = t * 128 + tid;
                int j = idx >> 3, q8 = idx & 7;
                cp16(&Ks[nb][j][q8 * 8], kb + (size_t)(c1 + j) * QKV + q8 * 8);
                cp16(&Vs[nb][j][q8 * 8], vb + (size_t)(c1 + j) * QKV + q8 * 8);
            }
            asm volatile("cp.async.commit_group;");
            asm volatile("cp.async.wait_group 1;");
        } else {
            asm volatile("cp.async.wait_group 0;");
        }
        __syncthreads();
        int bf = ci & 1;

        // S = Q @ K^T
        float s[2][8][4];
        #pragma unroll
        for (int mi = 0; mi < 2; mi++)
            #pragma unroll
            for (int ni = 0; ni < 8; ni++)
                #pragma unroll
                for (int t = 0; t < 4; t++) s[mi][ni][t] = 0.f;
        #pragma unroll
        for (int kk = 0; kk < 4; kk++) {
            u32 bfr[8][2];
            #pragma unroll
            for (int ni = 0; ni < 8; ni++)
                ldsm_x2(bfr[ni], &Ks[bf][ni * 8 + brow][kk * 16 + bkk]);
            #pragma unroll
            for (int mi = 0; mi < 2; mi++)
                #pragma unroll
                for (int ni = 0; ni < 8; ni++)
                    mma_bf16(s[mi][ni], qa[mi][kk], bfr[ni]);
        }

        // online softmax
        #pragma unroll
        for (int mi = 0; mi < 2; mi++) {
            float mx0 = -1e30f, mx1 = -1e30f;
            #pragma unroll
            for (int ni = 0; ni < 8; ni++) {
                #pragma unroll
                for (int t = 0; t < 4; t++) s[mi][ni][t] *= ATTN_SCALE;
                mx0 = fmaxf(mx0, fmaxf(s[mi][ni][0], s[mi][ni][1]));
                mx1 = fmaxf(mx1, fmaxf(s[mi][ni][2], s[mi][ni][3]));
            }
            mx0 = fmaxf(mx0, __shfl_xor_sync(0xffffffffu, mx0, 1));
            mx0 = fmaxf(mx0, __shfl_xor_sync(0xffffffffu, mx0, 2));
            mx1 = fmaxf(mx1, __shfl_xor_sync(0xffffffffu, mx1, 1));
            mx1 = fmaxf(mx1, __shfl_xor_sync(0xffffffffu, mx1, 2));
            float mn0 = fmaxf(mrow[mi][0], mx0);
            float mn1 = fmaxf(mrow[mi][1], mx1);
            float a0 = __expf(mrow[mi][0] - mn0);
            float a1 = __expf(mrow[mi][1] - mn1);
            float ps0 = 0.f, ps1 = 0.f;
            #pragma unroll
            for (int ni = 0; ni < 8; ni++) {
                s[mi][ni][0] = __expf(s[mi][ni][0] - mn0);
                s[mi][ni][1] = __expf(s[mi][ni][1] - mn0);
                s[mi][ni][2] = __expf(s[mi][ni][2] - mn1);
                s[mi][ni][3] = __expf(s[mi][ni][3] - mn1);
                ps0 += s[mi][ni][0] + s[mi][ni][1];
                ps1 += s[mi][ni][2] + s[mi][ni][3];
            }
            ps0 += __shfl_xor_sync(0xffffffffu, ps0, 1);
            ps0 += __shfl_xor_sync(0xffffffffu, ps0, 2);
            ps1 += __shfl_xor_sync(0xffffffffu, ps1, 1);
            ps1 += __shfl_xor_sync(0xffffffffu, ps1, 2);
            lrow[mi][0] = lrow[mi][0] * a0 + ps0;
            lrow[mi][1] = lrow[mi][1] * a1 + ps1;
            mrow[mi][0] = mn0;
            mrow[mi][1] = mn1;
            #pragma unroll
            for (int nd = 0; nd < 8; nd++) {
                o[mi][nd][0] *= a0; o[mi][nd][1] *= a0;
                o[mi][nd][2] *= a1; o[mi][nd][3] *= a1;
            }
        }

        // O += P @ V   (V fragments via ldmatrix.trans on [key][d] layout)
        #pragma unroll
        for (int kk = 0; kk < 4; kk++) {
            u32 pa[2][4];
            #pragma unroll
            for (int mi = 0; mi < 2; mi++) {
                pa[mi][0] = packbf2(s[mi][2 * kk][0],     s[mi][2 * kk][1]);
                pa[mi][1] = packbf2(s[mi][2 * kk][2],     s[mi][2 * kk][3]);
                pa[mi][2] = packbf2(s[mi][2 * kk + 1][0], s[mi][2 * kk + 1][1]);
                pa[mi][3] = packbf2(s[mi][2 * kk + 1][2], s[mi][2 * kk + 1][3]);
            }
            u32 vfr[8][2];
            #pragma unroll
            for (int nd = 0; nd < 8; nd++)
                ldsm_x2_trans(vfr[nd], &Vs[bf][kk * 16 + l16][nd * 8]);
            #pragma unroll
            for (int mi = 0; mi < 2; mi++)
                #pragma unroll
                for (int nd = 0; nd < 8; nd++)
                    mma_bf16(o[mi][nd], pa[mi], vfr[nd]);
        }
        __syncthreads();
    }

    // normalize + store
    #pragma unroll
    for (int mi = 0; mi < 2; mi++) {
        float inv0 = 1.0f / lrow[mi][0];
        float inv1 = 1.0f / lrow[mi][1];
        int r0 = half * 128 + wid * 32 + mi * 16 + gp;
        #pragma unroll
        for (int nd = 0; nd < 8; nd++) {
            int col = h * DD + nd * 8 + tin * 2;
            __nv_bfloat162 p0, p1;
            p0.x = __float2bfloat16(o[mi][nd][0] * inv0);
            p0.y = __float2bfloat16(o[mi][nd][1] * inv0);
            p1.x = __float2bfloat16(o[mi][nd][2] * inv1);
            p1.y = __float2bfloat16(o[mi][nd][3] * inv1);
            *(__nv_bfloat162*)&o_out[(tok0 + r0) * CC + col] = p0;
            *(__nv_bfloat162*)&o_out[(tok0 + r0 + 8) * CC + col] = p1;
        }
    }
}

// ---------------------------------------------------------------------------
extern "C" void kernel_launch(void* const* d_in, const int* in_sizes, int n_in,
                              void* d_out, int out_size)
{
    const float* x     = (const float*)d_in[0];
    const float* Wqkv  = (const float*)d_in[1];
    const float* Wproj = (const float*)d_in[2];
    const float* bproj = (const float*)d_in[3];
    const float* ln1g  = (const float*)d_in[4];
    const float* ln1b  = (const float*)d_in[5];
    const float* ln2g  = (const float*)d_in[6];
    const float* ln2b  = (const float*)d_in[7];
    const float* Wm1   = (const float*)d_in[8];
    const float* bm1   = (const float*)d_in[9];
    const float* Wm2   = (const float*)d_in[10];
    const float* bm2   = (const float*)d_in[11];
    float* out = (float*)d_out;

    float *p_xseq, *p_x2;
    bf16 *p_qkvb, *p_hb, *p_ab, *p_mb, *p_wq, *p_wp, *p_w1, *p_w2;
    cudaGetSymbolAddress((void**)&p_xseq, g_xseq);
    cudaGetSymbolAddress((void**)&p_x2,   g_x2);
    cudaGetSymbolAddress((void**)&p_qkvb, g_qkvb);
    cudaGetSymbolAddress((void**)&p_hb,   g_hb);
    cudaGetSymbolAddress((void**)&p_ab,   g_ab);
    cudaGetSymbolAddress((void**)&p_mb,   g_mb);
    cudaGetSymbolAddress((void**)&p_wq,   g_wq);
    cudaGetSymbolAddress((void**)&p_wp,   g_wp);
    cudaGetSymbolAddress((void**)&p_w1,   g_w1);
    cudaGetSymbolAddress((void**)&p_w2,   g_w2);

    dim3 tb(32, 8);
    k_f2b_all<<<(F2B_TOTAL + 255) / 256, 256>>>(Wqkv, p_wq, Wproj, p_wp, Wm1, p_w1, Wm2, p_w2);
    // 1) fused transpose-in + LN1 -> xseq fp32 + hb bf16
    k_tln<<<dim3(PP / 32, BB * NN), tb>>>(x, ln1g, ln1b, p_xseq, p_hb);
    // 2) qkv = h @ Wqkv^T (tensor cores, bf16 out)
    k_gemm_tc<0, 1> <<<dim3(QKV / 128, SS / 128), 256>>>(p_hb, p_wq, (const float*)0, (const float*)0, (float*)0, p_qkvb, CC, QKV);
    // 3) tensor-core flash attention -> bf16
    k_attn_tc<<<dim3(BB * NN, HH, 2), 128>>>(p_qkvb, p_ab);
    // 4) proj + bias + residual(x_seq) -> fp32 x2
    k_gemm_tc<3, 0> <<<dim3(CC / 128, SS / 128), 256>>>(p_ab, p_wp, bproj, p_xseq, p_x2, (bf16*)0, CC, CC);
    // 5) LN2 -> bf16
    k_layernorm<<<SS / 8, tb>>>(p_x2, ln2g, ln2b, p_hb);
    // 6) mlp1 + bias + gelu -> bf16
    k_gemm_tc<2, 1> <<<dim3(HID / 128, SS / 128), 256>>>(p_hb, p_w1, bm1, (const float*)0, (float*)0, p_mb, CC, HID);
    // 7) mlp2 + bias + residual(x2) + fused transpose-out -> out[B,C,N,P]
    k_gemm_tc<4, 0> <<<dim3(CC / 128, SS / 128), 256>>>(p_mb, p_w2, bm2, p_x2, out, (bf16*)0, HID, CC);
}

// round 17
// speedup vs baseline: 6.6130x; 1.0884x over previous
#include <cuda_runtime.h>
#include <cuda_bf16.h>
#include <math.h>
#include <stdint.h>

// Problem constants
#define BB   8
#define CC   256
#define NN   64
#define PP   256
#define SS   (BB * NN * PP)     // 131072 tokens
#define HH   4
#define DD   64
#define HID  512
#define QKV  768
#define ATTN_SCALE 0.125f
#define LN_EPS 1e-5f

typedef __nv_bfloat16 bf16;
typedef unsigned int u32;

// Scratch (static __device__ arrays: allocation-free per harness rules)
__device__ float g_xseq[(size_t)SS * CC];
__device__ float g_x2  [(size_t)SS * CC];
__device__ bf16  g_qkvb[(size_t)SS * QKV];
__device__ bf16  g_hb  [(size_t)SS * CC];
__device__ bf16  g_ab  [(size_t)SS * CC];
__device__ bf16  g_mb  [(size_t)SS * HID];
__device__ bf16  g_wq  [QKV * CC];
__device__ bf16  g_wp  [CC * CC];
__device__ bf16  g_w1  [HID * CC];
__device__ bf16  g_w2  [CC * HID];

// ---------------------------------------------------------------------------
__global__ void k_f2b_all(const float* __restrict__ s0, bf16* __restrict__ d0,
                          const float* __restrict__ s1, bf16* __restrict__ d1,
                          const float* __restrict__ s2, bf16* __restrict__ d2,
                          const float* __restrict__ s3, bf16* __restrict__ d3) {
    int i = blockIdx.x * 256 + threadIdx.x;
    if (i < QKV * CC) { d0[i] = __float2bfloat16(s0[i]); return; }
    i -= QKV * CC;
    if (i < CC * CC)  { d1[i] = __float2bfloat16(s1[i]); return; }
    i -= CC * CC;
    if (i < HID * CC) { d2[i] = __float2bfloat16(s2[i]); return; }
    i -= HID * CC;
    d3[i] = __float2bfloat16(s3[i]);
}
#define F2B_TOTAL (QKV * CC + CC * CC + HID * CC + CC * HID)

// ---------------------------------------------------------------------------
// Fused transpose-in + LN1
// ---------------------------------------------------------------------------
__global__ void k_tln(const float* __restrict__ x, const float* __restrict__ gamma,
                      const float* __restrict__ beta, float* __restrict__ xseq,
                      bf16* __restrict__ hb) {
    __shared__ float tile[256][33];
    int bn = blockIdx.y;
    int p0 = blockIdx.x * 32;
    int b = bn >> 6, n = bn & 63;
    int lane = threadIdx.x, wid = threadIdx.y;

    #pragma unroll
    for (int c = wid; c < 256; c += 8)
        tile[c][lane] = x[(((size_t)b * CC + c) * NN + n) * PP + p0 + lane];
    __syncthreads();

    #pragma unroll
    for (int t = 0; t < 4; t++) {
        int p = wid * 4 + t;
        float vals[8];
        float sum = 0.f, sq = 0.f;
        #pragma unroll
        for (int k = 0; k < 8; k++) {
            float v = tile[lane + k * 32][p];
            vals[k] = v; sum += v; sq += v * v;
        }
        #pragma unroll
        for (int o = 16; o; o >>= 1) {
            sum += __shfl_xor_sync(0xffffffffu, sum, o);
            sq  += __shfl_xor_sync(0xffffffffu, sq,  o);
        }
        float mu  = sum * (1.0f / CC);
        float var = sq * (1.0f / CC) - mu * mu;
        float inv = rsqrtf(var + LN_EPS);
        size_t row = ((size_t)bn * PP + p0 + p) * CC;
        #pragma unroll
        for (int k = 0; k < 8; k++) {
            int c = lane + k * 32;
            xseq[row + c] = vals[k];
            hb[row + c] = __float2bfloat16((vals[k] - mu) * inv * gamma[c] + beta[c]);
        }
    }
}

// ---------------------------------------------------------------------------
// LayerNorm (LN2)
// ---------------------------------------------------------------------------
__global__ void k_layernorm(const float* __restrict__ in, const float* __restrict__ gamma,
                            const float* __restrict__ beta, bf16* __restrict__ out) {
    int row = blockIdx.x * 8 + threadIdx.y;
    int lane = threadIdx.x;
    const float* r = in + (size_t)row * CC;
    float vals[8];
    float sum = 0.f, sq = 0.f;
    #pragma unroll
    for (int k = 0; k < 8; k++) {
        float t = r[lane + k * 32];
        vals[k] = t; sum += t; sq += t * t;
    }
    #pragma unroll
    for (int o = 16; o; o >>= 1) {
        sum += __shfl_xor_sync(0xffffffffu, sum, o);
        sq  += __shfl_xor_sync(0xffffffffu, sq,  o);
    }
    float mu  = sum * (1.0f / CC);
    float var = sq * (1.0f / CC) - mu * mu;
    float inv = rsqrtf(var + LN_EPS);
    bf16* w = out + (size_t)row * CC;
    #pragma unroll
    for (int k = 0; k < 8; k++) {
        int c = lane + k * 32;
        w[c] = __float2bfloat16((vals[k] - mu) * inv * gamma[c] + beta[c]);
    }
}

// ---------------------------------------------------------------------------
// MMA helpers
// ---------------------------------------------------------------------------
__device__ __forceinline__ float gelu_exact(float v) {
    return 0.5f * v * (1.0f + erff(v * 0.70710678118654752f));
}

#define ST 40   // GEMM smem row stride in bf16 elems (80B = 5*16B)

__device__ __forceinline__ void ldsm_x4(u32* r, const bf16* p) {
    u32 addr = (u32)__cvta_generic_to_shared((const void*)p);
    asm volatile("ldmatrix.sync.aligned.m8n8.x4.shared.b16 {%0,%1,%2,%3}, [%4];"
                 : "=r"(r[0]), "=r"(r[1]), "=r"(r[2]), "=r"(r[3]) : "r"(addr));
}
__device__ __forceinline__ void ldsm_x2(u32* r, const bf16* p) {
    u32 addr = (u32)__cvta_generic_to_shared((const void*)p);
    asm volatile("ldmatrix.sync.aligned.m8n8.x2.shared.b16 {%0,%1}, [%2];"
                 : "=r"(r[0]), "=r"(r[1]) : "r"(addr));
}
__device__ __forceinline__ void ldsm_x2_trans(u32* r, const bf16* p) {
    u32 addr = (u32)__cvta_generic_to_shared((const void*)p);
    asm volatile("ldmatrix.sync.aligned.m8n8.x2.trans.shared.b16 {%0,%1}, [%2];"
                 : "=r"(r[0]), "=r"(r[1]) : "r"(addr));
}
__device__ __forceinline__ void mma_bf16(float* c, const u32* a, const u32* b) {
    asm volatile("mma.sync.aligned.m16n8k16.row.col.f32.bf16.bf16.f32 "
                 "{%0,%1,%2,%3}, {%4,%5,%6,%7}, {%8,%9}, {%0,%1,%2,%3};"
                 : "+f"(c[0]), "+f"(c[1]), "+f"(c[2]), "+f"(c[3])
                 : "r"(a[0]), "r"(a[1]), "r"(a[2]), "r"(a[3]), "r"(b[0]), "r"(b[1]));
}
__device__ __forceinline__ u32 packbf2(float a, float b) {
    __nv_bfloat162 t = __float22bfloat162_rn(make_float2(a, b));
    return *(u32*)&t;
}
__device__ __forceinline__ void cp16(void* dst, const void* src) {
    u32 d = (u32)__cvta_generic_to_shared(dst);
    asm volatile("cp.async.ca.shared.global [%0], [%1], 16;" :: "r"(d), "l"(src));
}

// ---------------------------------------------------------------------------
// Tensor-core bf16 GEMM: out[m,n] = sum_k A[m,k]*W[n,k]  (+epilogue)
// BM=BN=128, BK=32, KT k-iters (K = 32*KT, compile-time -> fully unrolled).
// 2-stage cp.async ring, ONE __syncthreads per iter. 256 thr, 2 CTAs/SM.
// EPI: 0=none, 2=bias+gelu, 3=bias+residual, 4=bias+residual+transpose-out.
// ---------------------------------------------------------------------------
template<int EPI, int OUTBF, int KT>
__global__ __launch_bounds__(256, 2) void k_gemm_tc(
    const bf16* __restrict__ A, const bf16* __restrict__ W,
    const float* __restrict__ bias, const float* __restrict__ res,
    float* __restrict__ outf, bf16* __restrict__ outb, int O)
{
    const int K = KT * 32;
    __shared__ bf16 As[2][128 * ST];
    __shared__ bf16 Bs[2][128 * ST];
    int tid = threadIdx.x;
    int wid = tid >> 5, lane = tid & 31;
    int warp_m = wid >> 2, warp_n = wid & 3;
    int m0 = blockIdx.y * 128, n0 = blockIdx.x * 128;

    float acc[4][4][4];
    #pragma unroll
    for (int i = 0; i < 4; i++)
        #pragma unroll
        for (int j = 0; j < 4; j++)
            #pragma unroll
            for (int t = 0; t < 4; t++) acc[i][j][t] = 0.f;

    int lrw = tid >> 2, lcc = (tid & 3) * 8;
    const bf16* Abase = A + (size_t)(m0 + lrw) * K + lcc;
    const bf16* A64   = A + (size_t)(m0 + 64 + lrw) * K + lcc;
    const bf16* Wbase = W + (size_t)(n0 + lrw) * K + lcc;
    const bf16* W64   = W + (size_t)(n0 + 64 + lrw) * K + lcc;

    // prologue: stage 0
    cp16(&As[0][lrw * ST + lcc],        Abase);
    cp16(&As[0][(lrw + 64) * ST + lcc], A64);
    cp16(&Bs[0][lrw * ST + lcc],        Wbase);
    cp16(&Bs[0][(lrw + 64) * ST + lcc], W64);
    asm volatile("cp.async.commit_group;");

    int arow = (lane & 15), akk = (lane >> 4) * 8;
    int brow = (lane & 7),  bkk = ((lane >> 3) & 1) * 8;

    #pragma unroll
    for (int kt = 0; kt < KT; kt++) {
        // stage kt is the oldest pending group -> wait all
        asm volatile("cp.async.wait_group 0;");
        __syncthreads();
        // issue next stage AFTER the sync: buffer (kt+1)&1 was last read in
        // iter kt-1, and all its readers have passed this barrier.
        if (kt + 1 < KT) {
            int kb = (kt + 1) * 32;
            int nb = (kt + 1) & 1;
            cp16(&As[nb][lrw * ST + lcc],        Abase + kb);
            cp16(&As[nb][(lrw + 64) * ST + lcc], A64 + kb);
            cp16(&Bs[nb][lrw * ST + lcc],        Wbase + kb);
            cp16(&Bs[nb][(lrw + 64) * ST + lcc], W64 + kb);
            asm volatile("cp.async.commit_group;");
        }
        int bf = kt & 1;
        #pragma unroll
        for (int kk = 0; kk < 32; kk += 16) {
            u32 afr[4][4], bfr[4][2];
            #pragma unroll
            for (int mi = 0; mi < 4; mi++)
                ldsm_x4(afr[mi], &As[bf][(warp_m * 64 + mi * 16 + arow) * ST + kk + akk]);
            #pragma unroll
            for (int ni = 0; ni < 4; ni++)
                ldsm_x2(bfr[ni], &Bs[bf][(warp_n * 32 + ni * 8 + brow) * ST + kk + bkk]);
            #pragma unroll
            for (int mi = 0; mi < 4; mi++)
                #pragma unroll
                for (int ni = 0; ni < 4; ni++)
                    mma_bf16(acc[mi][ni], afr[mi], bfr[ni]);
        }
    }

    int gp = lane >> 2, tin = lane & 3;
    #pragma unroll
    for (int ni = 0; ni < 4; ni++) {
        int col = n0 + warp_n * 32 + ni * 8 + tin * 2;
        float bx = 0.f, by = 0.f;
        if (EPI >= 2) { float2 b2 = *(const float2*)&bias[col]; bx = b2.x; by = b2.y; }
        #pragma unroll
        for (int mi = 0; mi < 4; mi++) {
            int row = m0 + warp_m * 64 + mi * 16 + gp;
            #pragma unroll
            for (int half = 0; half < 2; half++) {
                int r = row + half * 8;
                float vx = acc[mi][ni][half * 2 + 0] + bx;
                float vy = acc[mi][ni][half * 2 + 1] + by;
                if (EPI == 2) { vx = gelu_exact(vx); vy = gelu_exact(vy); }
                if (EPI == 3 || EPI == 4) {
                    float2 rr = *(const float2*)&res[(size_t)r * O + col];
                    vx += rr.x; vy += rr.y;
                }
                if (EPI == 4) {
                    int bn = r >> 8, p = r & 255;
                    int b = bn >> 6, n = bn & 63;
                    outf[(((size_t)b * CC + col) * NN + n) * PP + p] = vx;
                    outf[(((size_t)b * CC + col + 1) * NN + n) * PP + p] = vy;
                } else if (OUTBF) {
                    __nv_bfloat162 p2;
                    p2.x = __float2bfloat16(vx); p2.y = __float2bfloat16(vy);
                    *(__nv_bfloat162*)&outb[(size_t)r * O + col] = p2;
                } else {
                    *(float2*)&outf[(size_t)r * O + col] = make_float2(vx, vy);
                }
            }
        }
    }
}

// ---------------------------------------------------------------------------
// Tensor-core flash attention (unchanged from R12 passing version)
// ---------------------------------------------------------------------------
__global__ __launch_bounds__(128) void k_attn_tc(const bf16* __restrict__ qkv,
                                                 bf16* __restrict__ o_out)
{
    __shared__ bf16 Ks[2][64][72];
    __shared__ bf16 Vs[2][64][72];

    int sq = blockIdx.x, h = blockIdx.y, half = blockIdx.z;
    int tid = threadIdx.x, wid = tid >> 5, lane = tid & 31;
    int gp = lane >> 2, tin = lane & 3;
    int brow = lane & 7, bkk = ((lane >> 3) & 1) * 8;
    int l16 = lane & 15;
    const size_t tok0 = (size_t)sq * PP;
    const bf16* qb = qkv + tok0 * QKV + h * DD;
    const bf16* kb = qkv + tok0 * QKV + 256 + h * DD;
    const bf16* vb = qkv + tok0 * QKV + 512 + h * DD;

    u32 qa[2][4][4];
    #pragma unroll
    for (int mi = 0; mi < 2; mi++) {
        int r0 = half * 128 + wid * 32 + mi * 16 + gp;
        #pragma unroll
        for (int kk = 0; kk < 4; kk++) {
            const bf16* p0 = qb + (size_t)r0 * QKV + kk * 16 + tin * 2;
            const bf16* p1 = qb + (size_t)(r0 + 8) * QKV + kk * 16 + tin * 2;
            qa[mi][kk][0] = *(const u32*)p0;
            qa[mi][kk][1] = *(const u32*)p1;
            qa[mi][kk][2] = *(const u32*)(p0 + 8);
            qa[mi][kk][3] = *(const u32*)(p1 + 8);
        }
    }

    #pragma unroll
    for (int t = 0; t < 4; t++) {
        int idx = t * 128 + tid;
        int j = idx >> 3, q8 = idx & 7;
        cp16(&Ks[0][j][q8 * 8], kb + (size_t)j * QKV + q8 * 8);
        cp16(&Vs[0][j][q8 * 8], vb + (size_t)j * QKV + q8 * 8);
    }
    asm volatile("cp.async.commit_group;");

    float o[2][8][4];
    #pragma unroll
    for (int mi = 0; mi < 2; mi++)
        #pragma unroll
        for (int nd = 0; nd < 8; nd++)
            #pragma unroll
            for (int t = 0; t < 4; t++) o[mi][nd][t] = 0.f;
    float mrow[2][2] = {{-1e30f, -1e30f}, {-1e30f, -1e30f}};
    float lrow[2][2] = {{0.f, 0.f}, {0.f, 0.f}};

    for (int ci = 0; ci < 4; ci++) {
        if (ci + 1 < 4) {
            int c1 = (ci + 1) * 64;
            int nb = (ci + 1) & 1;
            #pragma unroll
            for (int t = 0; t < 4; t++) {
                int idx = t * 128 + tid;
                int j = idx >> 3, q8 = idx & 7;
                cp16(&Ks[nb][j][q8 * 8], kb + (size_t)(c1 + j) * QKV + q8 * 8);
                cp16(&Vs[nb][j][q8 * 8], vb + (size_t)(c1 + j) * QKV + q8 * 8);
            }
            asm volatile("cp.async.commit_group;");
            asm volatile("cp.async.wait_group 1;");
        } else {
            asm volatile("cp.async.wait_group 0;");
        }
        __syncthreads();
        int bf = ci & 1;

        float s[2][8][4];
        #pragma unroll
        for (int mi = 0; mi < 2; mi++)
            #pragma unroll
            for (int ni = 0; ni < 8; ni++)
                #pragma unroll
                for (int t = 0; t < 4; t++) s[mi][ni][t] = 0.f;
        #pragma unroll
        for (int kk = 0; kk < 4; kk++) {
            u32 bfr[8][2];
            #pragma unroll
            for (int ni = 0; ni < 8; ni++)
                ldsm_x2(bfr[ni], &Ks[bf][ni * 8 + brow][kk * 16 + bkk]);
            #pragma unroll
            for (int mi = 0; mi < 2; mi++)
                #pragma unroll
                for (int ni = 0; ni < 8; ni++)
                    mma_bf16(s[mi][ni], qa[mi][kk], bfr[ni]);
        }

        #pragma unroll
        for (int mi = 0; mi < 2; mi++) {
            float mx0 = -1e30f, mx1 = -1e30f;
            #pragma unroll
            for (int ni = 0; ni < 8; ni++) {
                #pragma unroll
                for (int t = 0; t < 4; t++) s[mi][ni][t] *= ATTN_SCALE;
                mx0 = fmaxf(mx0, fmaxf(s[mi][ni][0], s[mi][ni][1]));
                mx1 = fmaxf(mx1, fmaxf(s[mi][ni][2], s[mi][ni][3]));
            }
            mx0 = fmaxf(mx0, __shfl_xor_sync(0xffffffffu, mx0, 1));
            mx0 = fmaxf(mx0, __shfl_xor_sync(0xffffffffu, mx0, 2));
            mx1 = fmaxf(mx1, __shfl_xor_sync(0xffffffffu, mx1, 1));
            mx1 = fmaxf(mx1, __shfl_xor_sync(0xffffffffu, mx1, 2));
            float mn0 = fmaxf(mrow[mi][0], mx0);
            float mn1 = fmaxf(mrow[mi][1], mx1);
            float a0 = __expf(mrow[mi][0] - mn0);
            float a1 = __expf(mrow[mi][1] - mn1);
            float ps0 = 0.f, ps1 = 0.f;
            #pragma unroll
            for (int ni = 0; ni < 8; ni++) {
                s[mi][ni][0] = __expf(s[mi][ni][0] - mn0);
                s[mi][ni][1] = __expf(s[mi][ni][1] - mn0);
                s[mi][ni][2] = __expf(s[mi][ni][2] - mn1);
                s[mi][ni][3] = __expf(s[mi][ni][3] - mn1);
                ps0 += s[mi][ni][0] + s[mi][ni][1];
                ps1 += s[mi][ni][2] + s[mi][ni][3];
            }
            ps0 += __shfl_xor_sync(0xffffffffu, ps0, 1);
            ps0 += __shfl_xor_sync(0xffffffffu, ps0, 2);
            ps1 += __shfl_xor_sync(0xffffffffu, ps1, 1);
            ps1 += __shfl_xor_sync(0xffffffffu, ps1, 2);
            lrow[mi][0] = lrow[mi][0] * a0 + ps0;
            lrow[mi][1] = lrow[mi][1] * a1 + ps1;
            mrow[mi][0] = mn0;
            mrow[mi][1] = mn1;
            #pragma unroll
            for (int nd = 0; nd < 8; nd++) {
                o[mi][nd][0] *= a0; o[mi][nd][1] *= a0;
                o[mi][nd][2] *= a1; o[mi][nd][3] *= a1;
            }
        }

        #pragma unroll
        for (int kk = 0; kk < 4; kk++) {
            u32 pa[2][4];
            #pragma unroll
            for (int mi = 0; mi < 2; mi++) {
                pa[mi][0] = packbf2(s[mi][2 * kk][0],     s[mi][2 * kk][1]);
                pa[mi][1] = packbf2(s[mi][2 * kk][2],     s[mi][2 * kk][3]);
                pa[mi][2] = packbf2(s[mi][2 * kk + 1][0], s[mi][2 * kk + 1][1]);
                pa[mi][3] = packbf2(s[mi][2 * kk + 1][2], s[mi][2 * kk + 1][3]);
            }
            u32 vfr[8][2];
            #pragma unroll
            for (int nd = 0; nd < 8; nd++)
                ldsm_x2_trans(vfr[nd], &Vs[bf][kk * 16 + l16][nd * 8]);
            #pragma unroll
            for (int mi = 0; mi < 2; mi++)
                #pragma unroll
                for (int nd = 0; nd < 8; nd++)
                    mma_bf16(o[mi][nd], pa[mi], vfr[nd]);
        }
        __syncthreads();
    }

    #pragma unroll
    for (int mi = 0; mi < 2; mi++) {
        float inv0 = 1.0f / lrow[mi][0];
        float inv1 = 1.0f / lrow[mi][1];
        int r0 = half * 128 + wid * 32 + mi * 16 + gp;
        #pragma unroll
        for (int nd = 0; nd < 8; nd++) {
            int col = h * DD + nd * 8 + tin * 2;
            __nv_bfloat162 p0, p1;
            p0.x = __float2bfloat16(o[mi][nd][0] * inv0);
            p0.y = __float2bfloat16(o[mi][nd][1] * inv0);
            p1.x = __float2bfloat16(o[mi][nd][2] * inv1);
            p1.y = __float2bfloat16(o[mi][nd][3] * inv1);
            *(__nv_bfloat162*)&o_out[(tok0 + r0) * CC + col] = p0;
            *(__nv_bfloat162*)&o_out[(tok0 + r0 + 8) * CC + col] = p1;
        }
    }
}

// ---------------------------------------------------------------------------
extern "C" void kernel_launch(void* const* d_in, const int* in_sizes, int n_in,
                              void* d_out, int out_size)
{
    const float* x     = (const float*)d_in[0];
    const float* Wqkv  = (const float*)d_in[1];
    const float* Wproj = (const float*)d_in[2];
    const float* bproj = (const float*)d_in[3];
    const float* ln1g  = (const float*)d_in[4];
    const float* ln1b  = (const float*)d_in[5];
    const float* ln2g  = (const float*)d_in[6];
    const float* ln2b  = (const float*)d_in[7];
    const float* Wm1   = (const float*)d_in[8];
    const float* bm1   = (const float*)d_in[9];
    const float* Wm2   = (const float*)d_in[10];
    const float* bm2   = (const float*)d_in[11];
    float* out = (float*)d_out;

    float *p_xseq, *p_x2;
    bf16 *p_qkvb, *p_hb, *p_ab, *p_mb, *p_wq, *p_wp, *p_w1, *p_w2;
    cudaGetSymbolAddress((void**)&p_xseq, g_xseq);
    cudaGetSymbolAddress((void**)&p_x2,   g_x2);
    cudaGetSymbolAddress((void**)&p_qkvb, g_qkvb);
    cudaGetSymbolAddress((void**)&p_hb,   g_hb);
    cudaGetSymbolAddress((void**)&p_ab,   g_ab);
    cudaGetSymbolAddress((void**)&p_mb,   g_mb);
    cudaGetSymbolAddress((void**)&p_wq,   g_wq);
    cudaGetSymbolAddress((void**)&p_wp,   g_wp);
    cudaGetSymbolAddress((void**)&p_w1,   g_w1);
    cudaGetSymbolAddress((void**)&p_w2,   g_w2);

    dim3 tb(32, 8);
    k_f2b_all<<<(F2B_TOTAL + 255) / 256, 256>>>(Wqkv, p_wq, Wproj, p_wp, Wm1, p_w1, Wm2, p_w2);
    // 1) fused transpose-in + LN1
    k_tln<<<dim3(PP / 32, BB * NN), tb>>>(x, ln1g, ln1b, p_xseq, p_hb);
    // 2) qkv (mma.sync, bf16 out), K=256 -> KT=8
    k_gemm_tc<0, 1, 8> <<<dim3(QKV / 128, SS / 128), 256>>>(p_hb, p_wq, (const float*)0, (const float*)0, (float*)0, p_qkvb, QKV);
    // 3) flash attention
    k_attn_tc<<<dim3(BB * NN, HH, 2), 128>>>(p_qkvb, p_ab);
    // 4) proj + bias + residual -> fp32 x2, K=256
    k_gemm_tc<3, 0, 8> <<<dim3(CC / 128, SS / 128), 256>>>(p_ab, p_wp, bproj, p_xseq, p_x2, (bf16*)0, CC);
    // 5) LN2
    k_layernorm<<<SS / 8, tb>>>(p_x2, ln2g, ln2b, p_hb);
    // 6) mlp1 + bias + gelu -> bf16, K=256
    k_gemm_tc<2, 1, 8> <<<dim3(HID / 128, SS / 128), 256>>>(p_hb, p_w1, bm1, (const float*)0, (float*)0, p_mb, HID);
    // 7) mlp2 + bias + residual + transpose-out, K=512 -> KT=16
    k_gemm_tc<4, 0, 16> <<<dim3(CC / 128, SS / 128), 256>>>(p_mb, p_w2, bm2, p_x2, out, (bf16*)0, CC);
}